// round 12
// baseline (speedup 1.0000x reference)
#include <cuda_runtime.h>
#include <cuda_bf16.h>
#include <math.h>
#include <stdint.h>

// Problem constants
#define MB  256
#define S   128
#define C   256
#define H   8
#define D   32
#define MROWS (MB*S)           // 32768
#define C2  (2*C)              // 512
#define NHB (MB*H)             // 2048
#define SSQ (S*S)              // 16384

// weight offsets inside the packed split-weight buffer
#define WOFF_O   196608         // 768*256
#define WOFF_0   262144         // + 256*256
#define WOFF_1   393216         // + 512*256   (total 524288)

// ---------------- scratch (device globals) ----------------
__device__ float g_v [MROWS*C];
__device__ float g_o [MROWS*C];
__device__ float g_e [NHB*SSQ];
__device__ float g_x1[MROWS*C];
__device__ float g_t2[MROWS*C2];
__device__ float g_psum[262144];
__device__ float g_psq [262144];
__device__ float g_scale[C2];
__device__ float g_shift[C2];
__device__ float g_scale_pe[SSQ];
__device__ float g_shift_pe[SSQ];
__device__ __nv_bfloat16 g_whi[524288];
__device__ __nv_bfloat16 g_wlo[524288];
__device__ __nv_bfloat16 g_qhi[MROWS*C];
__device__ __nv_bfloat16 g_qlo[MROWS*C];
__device__ __nv_bfloat16 g_khi[MROWS*C];
__device__ __nv_bfloat16 g_klo[MROWS*C];

// ---------------- BN stats: deterministic 2-stage reduction ----------------
__global__ void bn_partial(const float* __restrict__ X, int Cdim, int rowsPerBlock,
                           float* __restrict__ psum, float* __restrict__ psq) {
    int c = blockIdx.x * blockDim.x + threadIdx.x;
    int r0 = blockIdx.y * rowsPerBlock;
    float s = 0.f, q = 0.f;
    const float* Xp = X + (size_t)r0 * Cdim + c;
    for (int i = 0; i < rowsPerBlock; i++) {
        float v = Xp[(size_t)i * Cdim];
        s += v; q += v * v;
    }
    psum[(size_t)blockIdx.y * Cdim + c] = s;
    psq [(size_t)blockIdx.y * Cdim + c] = q;
}

// per-thread finalize (energy BN: many channels, few parts)
__global__ void bn_finalize(const float* __restrict__ psum, const float* __restrict__ psq,
                            int Cdim, int nparts, float invM,
                            const float* __restrict__ g, const float* __restrict__ b,
                            float* __restrict__ scale, float* __restrict__ shift) {
    int c = blockIdx.x * blockDim.x + threadIdx.x;
    float s = 0.f, q = 0.f;
    for (int p = 0; p < nparts; p++) {
        s += psum[(size_t)p * Cdim + c];
        q += psq [(size_t)p * Cdim + c];
    }
    float mean = s * invM;
    float var  = q * invM - mean * mean;
    float sc   = g[c] * rsqrtf(var + 1e-5f);
    scale[c] = sc;
    shift[c] = b[c] - mean * sc;
}

// warp-per-channel finalize (few channels, many parts)
__global__ void bn_finalize_warp(const float* __restrict__ psum, const float* __restrict__ psq,
                                 int Cdim, int nparts, float invM,
                                 const float* __restrict__ g, const float* __restrict__ b,
                                 float* __restrict__ scale, float* __restrict__ shift) {
    int warp = threadIdx.x >> 5, lane = threadIdx.x & 31;
    int c = blockIdx.x * 8 + warp;
    float s = 0.f, q = 0.f;
    for (int p = lane; p < nparts; p += 32) {
        s += psum[(size_t)p * Cdim + c];
        q += psq [(size_t)p * Cdim + c];
    }
    #pragma unroll
    for (int off = 16; off > 0; off >>= 1) {
        s += __shfl_xor_sync(0xffffffffu, s, off);
        q += __shfl_xor_sync(0xffffffffu, q, off);
    }
    if (lane == 0) {
        float mean = s * invM;
        float var  = q * invM - mean * mean;
        float sc   = g[c] * rsqrtf(var + 1e-5f);
        scale[c] = sc;
        shift[c] = b[c] - mean * sc;
    }
}

// ---------------- split helpers ----------------
__device__ __forceinline__ void split4(float4 v, __nv_bfloat16* hi, __nv_bfloat16* lo,
                                       size_t off) {
    __nv_bfloat16 h0 = __float2bfloat16(v.x), h1 = __float2bfloat16(v.y);
    __nv_bfloat16 h2 = __float2bfloat16(v.z), h3 = __float2bfloat16(v.w);
    *(__nv_bfloat162*)(hi + off)     = __nv_bfloat162(h0, h1);
    *(__nv_bfloat162*)(hi + off + 2) = __nv_bfloat162(h2, h3);
    *(__nv_bfloat162*)(lo + off) = __nv_bfloat162(
        __float2bfloat16(v.x - __bfloat162float(h0)),
        __float2bfloat16(v.y - __bfloat162float(h1)));
    *(__nv_bfloat162*)(lo + off + 2) = __nv_bfloat162(
        __float2bfloat16(v.z - __bfloat162float(h2)),
        __float2bfloat16(v.w - __bfloat162float(h3)));
}

__global__ void splitW_all(const float* __restrict__ Wq, const float* __restrict__ Wk,
                           const float* __restrict__ Wv, const float* __restrict__ Wo,
                           const float* __restrict__ W0, const float* __restrict__ W1,
                           __nv_bfloat16* __restrict__ hi, __nv_bfloat16* __restrict__ lo) {
    int i = blockIdx.x * blockDim.x + threadIdx.x;    // 0..131071
    const float* src; int local;
    if (i < 16384)       { src = Wq; local = i; }
    else if (i < 32768)  { src = Wk; local = i - 16384; }
    else if (i < 49152)  { src = Wv; local = i - 32768; }
    else if (i < 65536)  { src = Wo; local = i - 49152; }
    else if (i < 98304)  { src = W0; local = i - 65536; }
    else                 { src = W1; local = i - 98304; }
    split4(((const float4*)src)[local], hi, lo, (size_t)i * 4);
}

// ---------------- mma.sync / cp.async helpers ----------------
__device__ __forceinline__ uint32_t smem_u32(const void* p) {
    uint32_t a;
    asm("{ .reg .u64 t; cvta.to.shared.u64 t, %1; cvt.u32.u64 %0, t; }" : "=r"(a) : "l"(p));
    return a;
}
__device__ __forceinline__ void ldm_x4(uint32_t* r, uint32_t addr) {
    asm volatile("ldmatrix.sync.aligned.m8n8.x4.shared.b16 {%0,%1,%2,%3}, [%4];"
                 : "=r"(r[0]), "=r"(r[1]), "=r"(r[2]), "=r"(r[3]) : "r"(addr));
}
__device__ __forceinline__ void ldm_x2(uint32_t* r, uint32_t addr) {
    asm volatile("ldmatrix.sync.aligned.m8n8.x2.shared.b16 {%0,%1}, [%2];"
                 : "=r"(r[0]), "=r"(r[1]) : "r"(addr));
}
__device__ __forceinline__ void mma_bf16(float* c, const uint32_t* a, const uint32_t* b) {
    asm volatile(
        "mma.sync.aligned.m16n8k16.row.col.f32.bf16.bf16.f32 "
        "{%0,%1,%2,%3}, {%4,%5,%6,%7}, {%8,%9}, {%0,%1,%2,%3};"
        : "+f"(c[0]), "+f"(c[1]), "+f"(c[2]), "+f"(c[3])
        : "r"(a[0]), "r"(a[1]), "r"(a[2]), "r"(a[3]), "r"(b[0]), "r"(b[1]));
}
__device__ __forceinline__ void cp16(uint32_t dst, const void* src) {
    asm volatile("cp.async.cg.shared.global [%0], [%1], 16;" :: "r"(dst), "l"(src));
}
__device__ __forceinline__ void cp_commit() {
    asm volatile("cp.async.commit_group;" ::: "memory");
}
template<int N> __device__ __forceinline__ void cp_wait() {
    asm volatile("cp.async.wait_group %0;" :: "n"(N) : "memory");
}

// ---------------- fused split-bf16 GEMM, 128x128 tile, 4 warps --------------
// Cout[M,N] = split(op(A_f32))[M,K] @ (Bh+Bl)[N,K]^T  (+ bias, + residual)
// 4 warps as 2M x 2N, warp tile 64x64. K-chunk 32, 1-barrier pipeline.
// A: 2 stages (LDG->regs->affine/split->STS). B: 3 stages (cp.async).
// SMEM: [A: 2 x 20480][B: 3 x 20480][scales 4096] = 106496 B, 2 CTAs/SM.
#define ASTAGE 20480
#define BSTAGE 20480
#define AHALF  10240
#define B_BASE (2*ASTAGE)
#define SC_OFF (2*ASTAGE + 3*BSTAGE)
#define MMA_SMEM (SC_OFF + 4096)
#define GT 128                   // GEMM threads per CTA

template<int MODE, bool AFFINE, bool RELU, bool BIAS, bool RES>
__global__ void __launch_bounds__(GT, 2)
mma_gemm(const float* __restrict__ A,
         const float* __restrict__ scale, const float* __restrict__ shift,
         const __nv_bfloat16* __restrict__ b_hi, const __nv_bfloat16* __restrict__ b_lo,
         float* __restrict__ Cout,
         __nv_bfloat16* __restrict__ q_hi, __nv_bfloat16* __restrict__ q_lo,
         __nv_bfloat16* __restrict__ k_hi, __nv_bfloat16* __restrict__ k_lo,
         const float* __restrict__ bias, const float* __restrict__ res,
         int M_, int N_, int K_) {
    extern __shared__ __align__(16) char sb[];
    const uint32_t sb32 = smem_u32(sb);
    float* sSc = (float*)(sb + SC_OFF);
    float* sSh = (float*)(sb + SC_OFF + 2048);

    const int t = threadIdx.x;
    const int lane = t & 31, warp = t >> 5;
    const int wm = warp & 1, wn = warp >> 1;          // 2M x 2N
    const int row0 = blockIdx.y * 128, col0 = blockIdx.x * 128;

    if (AFFINE) {
        for (int i = t; i < K_; i += GT) { sSc[i] = scale[i]; sSh[i] = shift[i]; }
    }

    float acc[4][8][4];
    #pragma unroll
    for (int mi = 0; mi < 4; mi++)
        #pragma unroll
        for (int ni = 0; ni < 8; ni++)
            #pragma unroll
            for (int x = 0; x < 4; x++) acc[mi][ni][x] = 0.f;

    float4 aR[8];
    auto ldgA = [&](int k0) {
        #pragma unroll
        for (int i = 0; i < 8; i++) {
            int idx = t + i * GT;                   // 0..1023
            int r = idx >> 3, q = idx & 7;
            aR[i] = *(const float4*)&A[(size_t)(row0 + r) * K_ + k0 + q * 4];
        }
    };
    auto stsA = [&](int s, int k0) {
        char* base = sb + s * ASTAGE;
        #pragma unroll
        for (int i = 0; i < 8; i++) {
            int idx = t + i * GT;
            int r = idx >> 3, q = idx & 7;
            float4 v = aR[i];
            if (AFFINE) {
                int kc = k0 + q * 4;
                v.x = v.x * sSc[kc+0] + sSh[kc+0];
                v.y = v.y * sSc[kc+1] + sSh[kc+1];
                v.z = v.z * sSc[kc+2] + sSh[kc+2];
                v.w = v.w * sSc[kc+3] + sSh[kc+3];
                if (RELU) {
                    v.x = fmaxf(v.x, 0.f); v.y = fmaxf(v.y, 0.f);
                    v.z = fmaxf(v.z, 0.f); v.w = fmaxf(v.w, 0.f);
                }
            }
            __nv_bfloat16 h0 = __float2bfloat16(v.x), h1 = __float2bfloat16(v.y);
            __nv_bfloat16 h2 = __float2bfloat16(v.z), h3 = __float2bfloat16(v.w);
            __nv_bfloat162 hA(h0, h1), hB(h2, h3);
            __nv_bfloat162 lA(__float2bfloat16(v.x - __bfloat162float(h0)),
                              __float2bfloat16(v.y - __bfloat162float(h1)));
            __nv_bfloat162 lB(__float2bfloat16(v.z - __bfloat162float(h2)),
                              __float2bfloat16(v.w - __bfloat162float(h3)));
            int off = r * 80 + q * 8;
            *(__nv_bfloat162*)(base + off)             = hA;
            *(__nv_bfloat162*)(base + off + 4)         = hB;
            *(__nv_bfloat162*)(base + AHALF + off)     = lA;
            *(__nv_bfloat162*)(base + AHALF + off + 4) = lB;
        }
    };
    auto cpB = [&](int s, int k0) {
        uint32_t base = sb32 + B_BASE + s * BSTAGE;
        #pragma unroll
        for (int i = 0; i < 4; i++) {
            int idx = t + i * GT;                   // 0..511
            int r = idx >> 2, qq = idx & 3;
            uint32_t off = (uint32_t)(r * 80 + qq * 16);
            size_t gb = (size_t)(col0 + r) * K_ + k0 + qq * 8;
            cp16(base + off,         b_hi + gb);
            cp16(base + AHALF + off, b_lo + gb);
        }
        cp_commit();
    };
    auto compute = [&](int sa, int sbuf) {
        uint32_t abase = sb32 + sa * ASTAGE;
        uint32_t bbase = sb32 + B_BASE + sbuf * BSTAGE;
        #pragma unroll
        for (int kk = 0; kk < 2; kk++) {
            uint32_t bh[8][2], bl[8][2];
            #pragma unroll
            for (int ni = 0; ni < 8; ni++) {
                int r = wn * 64 + ni * 8 + (lane & 7);
                int cbyte = (kk * 16 + ((lane >> 3) & 1) * 8) * 2;
                uint32_t addr = bbase + r * 80 + cbyte;
                ldm_x2(bh[ni], addr);
                ldm_x2(bl[ni], addr + AHALF);
            }
            #pragma unroll
            for (int mi = 0; mi < 4; mi++) {
                uint32_t ah[4], al[4];
                int r = wm * 64 + mi * 16 + (lane & 15);
                int cbyte = (kk * 16 + ((lane >> 4) << 3)) * 2;
                uint32_t addr = abase + r * 80 + cbyte;
                ldm_x4(ah, addr);
                ldm_x4(al, addr + AHALF);
                #pragma unroll
                for (int ni = 0; ni < 8; ni++) {
                    mma_bf16(acc[mi][ni], ah, bh[ni]);
                    mma_bf16(acc[mi][ni], ah, bl[ni]);
                    mma_bf16(acc[mi][ni], al, bh[ni]);
                }
            }
        }
    };

    const int nchunk = K_ >> 5;
    ldgA(0);
    cpB(0, 0);
    if (nchunk > 1) cpB(1, 32);
    __syncthreads();                  // scales visible for stsA
    stsA(0, 0);
    if (nchunk > 1) ldgA(32);

    for (int ch = 0; ch < nchunk; ch++) {
        if (ch + 1 < nchunk) cp_wait<1>(); else cp_wait<0>();
        __syncthreads();
        if (ch + 1 < nchunk) stsA((ch + 1) & 1, (ch + 1) * 32);
        compute(ch & 1, ch % 3);
        if (ch + 2 < nchunk) {
            ldgA((ch + 2) * 32);
            cpB((ch + 2) % 3, (ch + 2) * 32);
        }
    }

    // ---- epilogue ----
    const int tr = lane >> 2, tc = (lane & 3) * 2;
    #pragma unroll
    for (int mi = 0; mi < 4; mi++) {
        #pragma unroll
        for (int ni = 0; ni < 8; ni++) {
            int rr = row0 + wm * 64 + mi * 16 + tr;
            int cc = col0 + wn * 64 + ni * 8 + tc;
            float v0 = acc[mi][ni][0], v1 = acc[mi][ni][1];
            float v2 = acc[mi][ni][2], v3 = acc[mi][ni][3];
            if (MODE == 2) {
                int dest = col0 >> 8;
                int ccl = cc - dest * 256;
                if (dest < 2) {
                    __nv_bfloat16* dh = (dest == 0) ? q_hi : k_hi;
                    __nv_bfloat16* dl = (dest == 0) ? q_lo : k_lo;
                    __nv_bfloat16 h0 = __float2bfloat16(v0), h1 = __float2bfloat16(v1);
                    __nv_bfloat16 h2 = __float2bfloat16(v2), h3 = __float2bfloat16(v3);
                    *(__nv_bfloat162*)(dh + (size_t)rr * 256 + ccl)     = __nv_bfloat162(h0, h1);
                    *(__nv_bfloat162*)(dh + (size_t)(rr+8) * 256 + ccl) = __nv_bfloat162(h2, h3);
                    *(__nv_bfloat162*)(dl + (size_t)rr * 256 + ccl) = __nv_bfloat162(
                        __float2bfloat16(v0 - __bfloat162float(h0)),
                        __float2bfloat16(v1 - __bfloat162float(h1)));
                    *(__nv_bfloat162*)(dl + (size_t)(rr+8) * 256 + ccl) = __nv_bfloat162(
                        __float2bfloat16(v2 - __bfloat162float(h2)),
                        __float2bfloat16(v3 - __bfloat162float(h3)));
                } else {
                    *(float2*)&Cout[(size_t)rr * 256 + ccl]     = make_float2(v0, v1);
                    *(float2*)&Cout[(size_t)(rr+8) * 256 + ccl] = make_float2(v2, v3);
                }
            } else {
                if (BIAS) { v0 += bias[cc]; v1 += bias[cc+1]; v2 += bias[cc]; v3 += bias[cc+1]; }
                if (RES) {
                    const float2 r0v = *(const float2*)&res[(size_t)rr * N_ + cc];
                    const float2 r1v = *(const float2*)&res[(size_t)(rr+8) * N_ + cc];
                    v0 += r0v.x; v1 += r0v.y; v2 += r1v.x; v3 += r1v.y;
                }
                *(float2*)&Cout[(size_t)rr * N_ + cc]     = make_float2(v0, v1);
                *(float2*)&Cout[(size_t)(rr+8) * N_ + cc] = make_float2(v2, v3);
            }
        }
    }
}

// ---------------- energy via mma.sync (fp32 output) ----------------
#define ETILE 10240
__global__ void __launch_bounds__(256, 2)
energy_mma(const __nv_bfloat16* __restrict__ qhi, const __nv_bfloat16* __restrict__ qlo,
           const __nv_bfloat16* __restrict__ khi, const __nv_bfloat16* __restrict__ klo,
           float* __restrict__ E) {
    __shared__ __align__(16) char sb[4 * ETILE];
    const uint32_t sb32 = smem_u32(sb);
    const int nh = blockIdx.x;
    const int n = nh >> 3, h = nh & 7;
    const int t = threadIdx.x;
    const int lane = t & 31, warp = t >> 5;
    const int wm = warp & 1, wn = warp >> 1;

    const __nv_bfloat16* qh = qhi + ((size_t)(n * S) * H + h) * D;
    const __nv_bfloat16* ql = qlo + ((size_t)(n * S) * H + h) * D;
    const __nv_bfloat16* kh = khi + ((size_t)(n * S) * H + h) * D;
    const __nv_bfloat16* kl = klo + ((size_t)(n * S) * H + h) * D;

    #pragma unroll
    for (int i = 0; i < 2; i++) {
        int idx = t + i * 256;
        int r = idx >> 2, qq = idx & 3;
        size_t g = (size_t)r * (H * D) + qq * 8;
        uint32_t off = (uint32_t)(r * 80 + qq * 16);
        cp16(sb32 + off,             qh + g);
        cp16(sb32 + ETILE   + off,   ql + g);
        cp16(sb32 + 2*ETILE + off,   kh + g);
        cp16(sb32 + 3*ETILE + off,   kl + g);
    }
    cp_commit();
    cp_wait<0>();
    __syncthreads();

    float acc[4][4][4];
    #pragma unroll
    for (int mi = 0; mi < 4; mi++)
        #pragma unroll
        for (int ni = 0; ni < 4; ni++)
            #pragma unroll
            for (int x = 0; x < 4; x++) acc[mi][ni][x] = 0.f;

    #pragma unroll
    for (int kk = 0; kk < 2; kk++) {
        uint32_t bh[4][2], bl[4][2];
        #pragma unroll
        for (int ni = 0; ni < 4; ni++) {
            int r = wn * 32 + ni * 8 + (lane & 7);
            int cbyte = (kk * 16 + ((lane >> 3) & 1) * 8) * 2;
            uint32_t addr = sb32 + 2*ETILE + r * 80 + cbyte;
            ldm_x2(bh[ni], addr);
            ldm_x2(bl[ni], addr + ETILE);
        }
        #pragma unroll
        for (int mi = 0; mi < 4; mi++) {
            uint32_t ah[4], al[4];
            int r = wm * 64 + mi * 16 + (lane & 15);
            int cbyte = (kk * 16 + ((lane >> 4) << 3)) * 2;
            uint32_t addr = sb32 + r * 80 + cbyte;
            ldm_x4(ah, addr);
            ldm_x4(al, addr + ETILE);
            #pragma unroll
            for (int ni = 0; ni < 4; ni++) {
                mma_bf16(acc[mi][ni], ah, bh[ni]);
                mma_bf16(acc[mi][ni], ah, bl[ni]);
                mma_bf16(acc[mi][ni], al, bh[ni]);
            }
        }
    }

    float* eb = E + (size_t)nh * SSQ;
    const int tr = lane >> 2, tc = (lane & 3) * 2;
    #pragma unroll
    for (int mi = 0; mi < 4; mi++)
        #pragma unroll
        for (int ni = 0; ni < 4; ni++) {
            int rr = wm * 64 + mi * 16 + tr;
            int cc = wn * 32 + ni * 8 + tc;
            *(float2*)&eb[(size_t)rr * S + cc]     = make_float2(acc[mi][ni][0], acc[mi][ni][1]);
            *(float2*)&eb[(size_t)(rr+8) * S + cc] = make_float2(acc[mi][ni][2], acc[mi][ni][3]);
        }
}

// ---------------- fused BN(affine) + softmax + AV, fp32 output --------------
#define SAV_SMEM (128*129*4 + 128*36*4)

typedef unsigned long long u64;
__device__ __forceinline__ u64 pack2(float x) {
    u64 r; unsigned u = __float_as_uint(x);
    asm("mov.b64 %0, {%1, %1};" : "=l"(r) : "r"(u));
    return r;
}
__device__ __forceinline__ void ffma2(u64& d, u64 a, u64 b) {
    asm("fma.rn.f32x2 %0, %1, %2, %0;" : "+l"(d) : "l"(a), "l"(b));
}
__device__ __forceinline__ float lo32(u64 v) { return __uint_as_float((unsigned)v); }
__device__ __forceinline__ float hi32(u64 v) { return __uint_as_float((unsigned)(v >> 32)); }

__global__ void __launch_bounds__(256, 2)
softmax_av(const float* __restrict__ E,
           const float* __restrict__ scpe, const float* __restrict__ shpe,
           const float* __restrict__ V, float* __restrict__ O) {
    extern __shared__ __align__(16) float smf[];
    float* attn = smf;
    float* vs   = smf + 128 * 129;
    const int nh = blockIdx.x;
    const int n = nh >> 3, h = nh & 7;
    const int t = threadIdx.x;
    const int lane = t & 31, warp = t >> 5;

    const float* vb = V + ((size_t)(n * S) * H + h) * D;
    #pragma unroll
    for (int i = 0; i < 4; i++) {
        int idx = t + i * 256;
        int l = idx >> 3, qq = idx & 7;
        *(float4*)&vs[l * 36 + qq * 4] = *(const float4*)&vb[(size_t)l * (H * D) + qq * 4];
    }

    const float* eb = E + (size_t)nh * SSQ;
    for (int rr = 0; rr < 16; rr++) {
        int row = warp * 16 + rr;
        const float* e = eb + (size_t)row * S;
        const float* sc = scpe + row * S;
        const float* sh = shpe + row * S;
        float v[4];
        float mx = -INFINITY;
        #pragma unroll
        for (int i = 0; i < 4; i++) {
            int ki = i * 32 + lane;
            v[i] = (e[ki] * sc[ki] + sh[ki]) * 0.0625f;
            mx = fmaxf(mx, v[i]);
        }
        #pragma unroll
        for (int off = 16; off > 0; off >>= 1)
            mx = fmaxf(mx, __shfl_xor_sync(0xffffffffu, mx, off));
        float sum = 0.f;
        #pragma unroll
        for (int i = 0; i < 4; i++) { v[i] = __expf(v[i] - mx); sum += v[i]; }
        #pragma unroll
        for (int off = 16; off > 0; off >>= 1)
            sum += __shfl_xor_sync(0xffffffffu, sum, off);
        float inv = 1.f / sum;
        #pragma unroll
        for (int i = 0; i < 4; i++)
            attn[row * 129 + i * 32 + lane] = v[i] * inv;
    }
    __syncthreads();

    const int ty = t >> 3, tx = t & 7;
    u64 acc[4][2];
    #pragma unroll
    for (int i = 0; i < 4; i++) { acc[i][0] = 0ull; acc[i][1] = 0ull; }
    for (int l = 0; l < 128; l++) {
        u64 b0 = *(const u64*)&vs[l * 36 + tx * 4];
        u64 b1 = *(const u64*)&vs[l * 36 + tx * 4 + 2];
        #pragma unroll
        for (int i = 0; i < 4; i++) {
            u64 ad = pack2(attn[(ty * 4 + i) * 129 + l]);
            ffma2(acc[i][0], ad, b0);
            ffma2(acc[i][1], ad, b1);
        }
    }
    #pragma unroll
    for (int i = 0; i < 4; i++) {
        int qrow = ty * 4 + i;
        size_t base = ((size_t)(n * S + qrow) * H + h) * D + tx * 4;
        *(float4*)&O[base] = make_float4(lo32(acc[i][0]), hi32(acc[i][0]),
                                         lo32(acc[i][1]), hi32(acc[i][1]));
    }
}

// ---------------------------------------------------------------------------
extern "C" void kernel_launch(void* const* d_in, const int* in_sizes, int n_in,
                              void* d_out, int out_size) {
    const float* x    = (const float*)d_in[0];
    const float* g_n  = (const float*)d_in[1];
    const float* b_n  = (const float*)d_in[2];
    const float* Wq   = (const float*)d_in[3];
    const float* Wk   = (const float*)d_in[4];
    const float* Wv   = (const float*)d_in[5];
    const float* Wo   = (const float*)d_in[6];
    const float* bo   = (const float*)d_in[7];
    const float* g_pe = (const float*)d_in[8];
    const float* b_pe = (const float*)d_in[9];
    const float* g0   = (const float*)d_in[10];
    const float* b0   = (const float*)d_in[11];
    const float* W0   = (const float*)d_in[12];
    const float* g1   = (const float*)d_in[13];
    const float* b1   = (const float*)d_in[14];
    const float* W1   = (const float*)d_in[15];
    float* out = (float*)d_out;

    float *v, *o, *e, *x1, *t2, *psum, *psq, *sc, *sh, *scpe, *shpe;
    __nv_bfloat16 *whi, *wlo, *qhi, *qlo, *khi, *klo;
    cudaGetSymbolAddress((void**)&v,    g_v);
    cudaGetSymbolAddress((void**)&o,    g_o);
    cudaGetSymbolAddress((void**)&e,    g_e);
    cudaGetSymbolAddress((void**)&x1,   g_x1);
    cudaGetSymbolAddress((void**)&t2,   g_t2);
    cudaGetSymbolAddress((void**)&psum, g_psum);
    cudaGetSymbolAddress((void**)&psq,  g_psq);
    cudaGetSymbolAddress((void**)&sc,   g_scale);
    cudaGetSymbolAddress((void**)&sh,   g_shift);
    cudaGetSymbolAddress((void**)&scpe, g_scale_pe);
    cudaGetSymbolAddress((void**)&shpe, g_shift_pe);
    cudaGetSymbolAddress((void**)&whi,  g_whi);
    cudaGetSymbolAddress((void**)&wlo,  g_wlo);
    cudaGetSymbolAddress((void**)&qhi,  g_qhi);
    cudaGetSymbolAddress((void**)&qlo,  g_qlo);
    cudaGetSymbolAddress((void**)&khi,  g_khi);
    cudaGetSymbolAddress((void**)&klo,  g_klo);

    cudaFuncSetAttribute(mma_gemm<2,true ,false,false,false>, cudaFuncAttributeMaxDynamicSharedMemorySize, MMA_SMEM);
    cudaFuncSetAttribute(mma_gemm<0,false,false,true ,true >, cudaFuncAttributeMaxDynamicSharedMemorySize, MMA_SMEM);
    cudaFuncSetAttribute(mma_gemm<0,true ,true ,false,false>, cudaFuncAttributeMaxDynamicSharedMemorySize, MMA_SMEM);
    cudaFuncSetAttribute(mma_gemm<0,true ,true ,false,true >, cudaFuncAttributeMaxDynamicSharedMemorySize, MMA_SMEM);
    cudaFuncSetAttribute(softmax_av, cudaFuncAttributeMaxDynamicSharedMemorySize, SAV_SMEM);

    // split all weights (one launch, no deps)
    splitW_all<<<512, 256>>>(Wq, Wk, Wv, Wo, W0, W1, whi, wlo);

    // BN over C on x
    bn_partial<<<dim3(1, 256), 256>>>(x, C, 128, psum, psq);
    bn_finalize_warp<<<C / 8, 256>>>(psum, psq, C, 256, 1.f / MROWS, g_n, b_n, sc, sh);

    // fused QKV GEMM (128-col tiles: tiles 0-1 -> q, 2-3 -> k, 4-5 -> v)
    dim3 gq(768 / 128, MROWS / 128);
    mma_gemm<2,true,false,false,false><<<gq, GT, MMA_SMEM>>>(x, sc, sh, whi, wlo,
        v, qhi, qlo, khi, klo, nullptr, nullptr, MROWS, 768, C);

    // energy (fp32 out)
    energy_mma<<<NHB, 256>>>(qhi, qlo, khi, klo, e);

    // BN over S*S on energy
    bn_partial<<<dim3(SSQ / 256, 8), 256>>>(e, SSQ, 256, psum, psq);
    bn_finalize<<<SSQ / 256, 256>>>(psum, psq, SSQ, 8, 1.f / NHB, g_pe, b_pe, scpe, shpe);

    // fused BN + softmax + AV -> fp32 o
    softmax_av<<<NHB, 256, SAV_SMEM>>>(e, scpe, shpe, v, o);

    // x1 = o @ Wo^T + bo + x
    dim3 go(C / 128, MROWS / 128);
    mma_gemm<0,false,false,true,true><<<go, GT, MMA_SMEM>>>(o, nullptr, nullptr,
        whi + WOFF_O, wlo + WOFF_O, x1, nullptr, nullptr, nullptr, nullptr, bo, x, MROWS, C, C);

    // FFN: BN0 stats, fused affine+relu inside FFN0 GEMM
    bn_partial<<<dim3(1, 256), 256>>>(x1, C, 128, psum, psq);
    bn_finalize_warp<<<C / 8, 256>>>(psum, psq, C, 256, 1.f / MROWS, g0, b0, sc, sh);
    dim3 gf0(C2 / 128, MROWS / 128);
    mma_gemm<0,true,true,false,false><<<gf0, GT, MMA_SMEM>>>(x1, sc, sh,
        whi + WOFF_0, wlo + WOFF_0, t2, nullptr, nullptr, nullptr, nullptr, nullptr, nullptr, MROWS, C2, C);

    // BN1 stats, fused affine+relu inside FFN1 GEMM, + x1
    bn_partial<<<dim3(2, 256), 256>>>(t2, C2, 128, psum, psq);
    bn_finalize_warp<<<C2 / 8, 256>>>(psum, psq, C2, 256, 1.f / MROWS, g1, b1, sc, sh);
    mma_gemm<0,true,true,false,true><<<go, GT, MMA_SMEM>>>(t2, sc, sh,
        whi + WOFF_1, wlo + WOFF_1, out, nullptr, nullptr, nullptr, nullptr, nullptr, x1, MROWS, C, C2);
}

// round 14
// speedup vs baseline: 1.0476x; 1.0476x over previous
#include <cuda_runtime.h>
#include <cuda_bf16.h>
#include <math.h>
#include <stdint.h>

// Problem constants
#define MB  256
#define S   128
#define C   256
#define H   8
#define D   32
#define MROWS (MB*S)           // 32768
#define C2  (2*C)              // 512
#define NHB (MB*H)             // 2048
#define SSQ (S*S)              // 16384

// weight offsets inside the packed split-weight buffer
#define WOFF_O   196608         // 768*256
#define WOFF_0   262144         // + 256*256
#define WOFF_1   393216         // + 512*256   (total 524288)

// ---------------- scratch (device globals) ----------------
__device__ float g_v [MROWS*C];
__device__ float g_o [MROWS*C];
__device__ float g_e [NHB*SSQ];
__device__ float g_x1[MROWS*C];
__device__ float g_t2[MROWS*C2];
__device__ float g_psum[262144];
__device__ float g_psq [262144];
__device__ float g_scale[C2];
__device__ float g_shift[C2];
__device__ float g_scale_pe[SSQ];
__device__ float g_shift_pe[SSQ];
__device__ __nv_bfloat16 g_whi[524288];
__device__ __nv_bfloat16 g_wlo[524288];
__device__ __nv_bfloat16 g_qhi[MROWS*C];
__device__ __nv_bfloat16 g_qlo[MROWS*C];
__device__ __nv_bfloat16 g_khi[MROWS*C];
__device__ __nv_bfloat16 g_klo[MROWS*C];

// ---------------- BN stats: deterministic 2-stage reduction ----------------
__global__ void bn_partial(const float* __restrict__ X, int Cdim, int rowsPerBlock,
                           float* __restrict__ psum, float* __restrict__ psq) {
    int c = blockIdx.x * blockDim.x + threadIdx.x;
    int r0 = blockIdx.y * rowsPerBlock;
    float s = 0.f, q = 0.f;
    const float* Xp = X + (size_t)r0 * Cdim + c;
    for (int i = 0; i < rowsPerBlock; i++) {
        float v = Xp[(size_t)i * Cdim];
        s += v; q += v * v;
    }
    psum[(size_t)blockIdx.y * Cdim + c] = s;
    psq [(size_t)blockIdx.y * Cdim + c] = q;
}

// per-thread finalize (energy BN: many channels, few parts)
__global__ void bn_finalize(const float* __restrict__ psum, const float* __restrict__ psq,
                            int Cdim, int nparts, float invM,
                            const float* __restrict__ g, const float* __restrict__ b,
                            float* __restrict__ scale, float* __restrict__ shift) {
    int c = blockIdx.x * blockDim.x + threadIdx.x;
    float s = 0.f, q = 0.f;
    for (int p = 0; p < nparts; p++) {
        s += psum[(size_t)p * Cdim + c];
        q += psq [(size_t)p * Cdim + c];
    }
    float mean = s * invM;
    float var  = q * invM - mean * mean;
    float sc   = g[c] * rsqrtf(var + 1e-5f);
    scale[c] = sc;
    shift[c] = b[c] - mean * sc;
}

// warp-per-channel finalize (few channels, many parts)
__global__ void bn_finalize_warp(const float* __restrict__ psum, const float* __restrict__ psq,
                                 int Cdim, int nparts, float invM,
                                 const float* __restrict__ g, const float* __restrict__ b,
                                 float* __restrict__ scale, float* __restrict__ shift) {
    int warp = threadIdx.x >> 5, lane = threadIdx.x & 31;
    int c = blockIdx.x * 8 + warp;
    float s = 0.f, q = 0.f;
    for (int p = lane; p < nparts; p += 32) {
        s += psum[(size_t)p * Cdim + c];
        q += psq [(size_t)p * Cdim + c];
    }
    #pragma unroll
    for (int off = 16; off > 0; off >>= 1) {
        s += __shfl_xor_sync(0xffffffffu, s, off);
        q += __shfl_xor_sync(0xffffffffu, q, off);
    }
    if (lane == 0) {
        float mean = s * invM;
        float var  = q * invM - mean * mean;
        float sc   = g[c] * rsqrtf(var + 1e-5f);
        scale[c] = sc;
        shift[c] = b[c] - mean * sc;
    }
}

// ---------------- split helpers ----------------
__device__ __forceinline__ void split4(float4 v, __nv_bfloat16* hi, __nv_bfloat16* lo,
                                       size_t off) {
    __nv_bfloat16 h0 = __float2bfloat16(v.x), h1 = __float2bfloat16(v.y);
    __nv_bfloat16 h2 = __float2bfloat16(v.z), h3 = __float2bfloat16(v.w);
    *(__nv_bfloat162*)(hi + off)     = __nv_bfloat162(h0, h1);
    *(__nv_bfloat162*)(hi + off + 2) = __nv_bfloat162(h2, h3);
    *(__nv_bfloat162*)(lo + off) = __nv_bfloat162(
        __float2bfloat16(v.x - __bfloat162float(h0)),
        __float2bfloat16(v.y - __bfloat162float(h1)));
    *(__nv_bfloat162*)(lo + off + 2) = __nv_bfloat162(
        __float2bfloat16(v.z - __bfloat162float(h2)),
        __float2bfloat16(v.w - __bfloat162float(h3)));
}

__global__ void splitW_all(const float* __restrict__ Wq, const float* __restrict__ Wk,
                           const float* __restrict__ Wv, const float* __restrict__ Wo,
                           const float* __restrict__ W0, const float* __restrict__ W1,
                           __nv_bfloat16* __restrict__ hi, __nv_bfloat16* __restrict__ lo) {
    int i = blockIdx.x * blockDim.x + threadIdx.x;    // 0..131071
    const float* src; int local;
    if (i < 16384)       { src = Wq; local = i; }
    else if (i < 32768)  { src = Wk; local = i - 16384; }
    else if (i < 49152)  { src = Wv; local = i - 32768; }
    else if (i < 65536)  { src = Wo; local = i - 49152; }
    else if (i < 98304)  { src = W0; local = i - 65536; }
    else                 { src = W1; local = i - 98304; }
    split4(((const float4*)src)[local], hi, lo, (size_t)i * 4);
}

// ---------------- mma.sync / cp.async helpers ----------------
__device__ __forceinline__ uint32_t smem_u32(const void* p) {
    uint32_t a;
    asm("{ .reg .u64 t; cvta.to.shared.u64 t, %1; cvt.u32.u64 %0, t; }" : "=r"(a) : "l"(p));
    return a;
}
__device__ __forceinline__ void ldm_x4(uint32_t* r, uint32_t addr) {
    asm volatile("ldmatrix.sync.aligned.m8n8.x4.shared.b16 {%0,%1,%2,%3}, [%4];"
                 : "=r"(r[0]), "=r"(r[1]), "=r"(r[2]), "=r"(r[3]) : "r"(addr));
}
__device__ __forceinline__ void mma_bf16(float* c, const uint32_t* a, const uint32_t* b) {
    asm volatile(
        "mma.sync.aligned.m16n8k16.row.col.f32.bf16.bf16.f32 "
        "{%0,%1,%2,%3}, {%4,%5,%6,%7}, {%8,%9}, {%0,%1,%2,%3};"
        : "+f"(c[0]), "+f"(c[1]), "+f"(c[2]), "+f"(c[3])
        : "r"(a[0]), "r"(a[1]), "r"(a[2]), "r"(a[3]), "r"(b[0]), "r"(b[1]));
}
__device__ __forceinline__ void cp16(uint32_t dst, const void* src) {
    asm volatile("cp.async.cg.shared.global [%0], [%1], 16;" :: "r"(dst), "l"(src));
}
__device__ __forceinline__ void cp_commit() {
    asm volatile("cp.async.commit_group;" ::: "memory");
}
template<int N> __device__ __forceinline__ void cp_wait() {
    asm volatile("cp.async.wait_group %0;" :: "n"(N) : "memory");
}

// ---------------- fused split-bf16 GEMM, 128x128 tile, 1-barrier pipeline ---
// Cout[M,N] = split(op(A_f32))[M,K] @ (Bh+Bl)[N,K]^T  (+ bias, + residual)
// 8 warps 2M x 4N (warp 64x32), K-chunk 32.
// A: 2 stages (LDG->regs->affine/split->STS). B: 3 stages (cp.async).
// B hi/lo fragments fetched with ONE ldmatrix.x4 (lanes 0-15 -> Bhi rows,
// lanes 16-31 -> Blo rows) instead of two ldm_x2.
// SMEM: [A: 2 x 20480][B: 3 x 20480][scales 4096] = 106496 B, 2 CTAs/SM.
#define ASTAGE 20480
#define BSTAGE 20480
#define AHALF  10240
#define B_BASE (2*ASTAGE)
#define SC_OFF (2*ASTAGE + 3*BSTAGE)
#define MMA_SMEM (SC_OFF + 4096)

template<int MODE, bool AFFINE, bool RELU, bool BIAS, bool RES>
__global__ void __launch_bounds__(256, 2)
mma_gemm(const float* __restrict__ A,
         const float* __restrict__ scale, const float* __restrict__ shift,
         const __nv_bfloat16* __restrict__ b_hi, const __nv_bfloat16* __restrict__ b_lo,
         float* __restrict__ Cout,
         __nv_bfloat16* __restrict__ q_hi, __nv_bfloat16* __restrict__ q_lo,
         __nv_bfloat16* __restrict__ k_hi, __nv_bfloat16* __restrict__ k_lo,
         const float* __restrict__ bias, const float* __restrict__ res,
         int M_, int N_, int K_) {
    extern __shared__ __align__(16) char sb[];
    const uint32_t sb32 = smem_u32(sb);
    float* sSc = (float*)(sb + SC_OFF);
    float* sSh = (float*)(sb + SC_OFF + 2048);

    const int t = threadIdx.x;
    const int lane = t & 31, warp = t >> 5;
    const int wm = warp & 1, wn = warp >> 1;
    const int row0 = blockIdx.y * 128, col0 = blockIdx.x * 128;

    if (AFFINE) {
        for (int i = t; i < K_; i += 256) { sSc[i] = scale[i]; sSh[i] = shift[i]; }
    }

    float acc[4][4][4];
    #pragma unroll
    for (int mi = 0; mi < 4; mi++)
        #pragma unroll
        for (int ni = 0; ni < 4; ni++)
            #pragma unroll
            for (int x = 0; x < 4; x++) acc[mi][ni][x] = 0.f;

    float4 aR[4];
    auto ldgA = [&](int k0) {
        #pragma unroll
        for (int i = 0; i < 4; i++) {
            int idx = t + i * 256;
            int r = idx >> 3, q = idx & 7;
            aR[i] = *(const float4*)&A[(size_t)(row0 + r) * K_ + k0 + q * 4];
        }
    };
    auto stsA = [&](int s, int k0) {
        char* base = sb + s * ASTAGE;
        #pragma unroll
        for (int i = 0; i < 4; i++) {
            int idx = t + i * 256;
            int r = idx >> 3, q = idx & 7;
            float4 v = aR[i];
            if (AFFINE) {
                int kc = k0 + q * 4;
                v.x = v.x * sSc[kc+0] + sSh[kc+0];
                v.y = v.y * sSc[kc+1] + sSh[kc+1];
                v.z = v.z * sSc[kc+2] + sSh[kc+2];
                v.w = v.w * sSc[kc+3] + sSh[kc+3];
                if (RELU) {
                    v.x = fmaxf(v.x, 0.f); v.y = fmaxf(v.y, 0.f);
                    v.z = fmaxf(v.z, 0.f); v.w = fmaxf(v.w, 0.f);
                }
            }
            __nv_bfloat16 h0 = __float2bfloat16(v.x), h1 = __float2bfloat16(v.y);
            __nv_bfloat16 h2 = __float2bfloat16(v.z), h3 = __float2bfloat16(v.w);
            __nv_bfloat162 hA(h0, h1), hB(h2, h3);
            __nv_bfloat162 lA(__float2bfloat16(v.x - __bfloat162float(h0)),
                              __float2bfloat16(v.y - __bfloat162float(h1)));
            __nv_bfloat162 lB(__float2bfloat16(v.z - __bfloat162float(h2)),
                              __float2bfloat16(v.w - __bfloat162float(h3)));
            int off = r * 80 + q * 8;
            *(__nv_bfloat162*)(base + off)             = hA;
            *(__nv_bfloat162*)(base + off + 4)         = hB;
            *(__nv_bfloat162*)(base + AHALF + off)     = lA;
            *(__nv_bfloat162*)(base + AHALF + off + 4) = lB;
        }
    };
    auto cpB = [&](int s, int k0) {
        uint32_t base = sb32 + B_BASE + s * BSTAGE;
        #pragma unroll
        for (int i = 0; i < 2; i++) {
            int idx = t + i * 256;
            int r = idx >> 2, qq = idx & 3;
            uint32_t off = (uint32_t)(r * 80 + qq * 16);
            size_t gb = (size_t)(col0 + r) * K_ + k0 + qq * 8;
            cp16(base + off,         b_hi + gb);
            cp16(base + AHALF + off, b_lo + gb);
        }
        cp_commit();
    };
    auto compute = [&](int sa, int sbuf) {
        uint32_t abase = sb32 + sa * ASTAGE;
        uint32_t bbase = sb32 + B_BASE + sbuf * BSTAGE;
        #pragma unroll
        for (int kk = 0; kk < 2; kk++) {
            uint32_t bf[4][4];    // [ni][0,1]=Bhi frag, [2,3]=Blo frag
            #pragma unroll
            for (int ni = 0; ni < 4; ni++) {
                int r = wn * 32 + ni * 8 + (lane & 7);
                int cbyte = (kk * 16 + ((lane >> 3) & 1) * 8) * 2;
                uint32_t addr = bbase + r * 80 + cbyte + ((lane & 16) ? AHALF : 0);
                ldm_x4(bf[ni], addr);
            }
            #pragma unroll
            for (int mi = 0; mi < 4; mi++) {
                uint32_t ah[4], al[4];
                int r = wm * 64 + mi * 16 + (lane & 15);
                int cbyte = (kk * 16 + ((lane >> 4) << 3)) * 2;
                uint32_t addr = abase + r * 80 + cbyte;
                ldm_x4(ah, addr);
                ldm_x4(al, addr + AHALF);
                #pragma unroll
                for (int ni = 0; ni < 4; ni++) {
                    mma_bf16(acc[mi][ni], ah, &bf[ni][0]);
                    mma_bf16(acc[mi][ni], ah, &bf[ni][2]);
                    mma_bf16(acc[mi][ni], al, &bf[ni][0]);
                }
            }
        }
    };

    const int nchunk = K_ >> 5;
    ldgA(0);
    cpB(0, 0);
    if (nchunk > 1) cpB(1, 32);
    __syncthreads();                  // scales visible for stsA
    stsA(0, 0);
    if (nchunk > 1) ldgA(32);

    for (int ch = 0; ch < nchunk; ch++) {
        if (ch + 1 < nchunk) cp_wait<1>(); else cp_wait<0>();
        __syncthreads();
        if (ch + 1 < nchunk) stsA((ch + 1) & 1, (ch + 1) * 32);
        compute(ch & 1, ch % 3);
        if (ch + 2 < nchunk) {
            ldgA((ch + 2) * 32);
            cpB((ch + 2) % 3, (ch + 2) * 32);
        }
    }

    // ---- epilogue ----
    const int tr = lane >> 2, tc = (lane & 3) * 2;
    #pragma unroll
    for (int mi = 0; mi < 4; mi++) {
        #pragma unroll
        for (int ni = 0; ni < 4; ni++) {
            int rr = row0 + wm * 64 + mi * 16 + tr;
            int cc = col0 + wn * 32 + ni * 8 + tc;
            float v0 = acc[mi][ni][0], v1 = acc[mi][ni][1];
            float v2 = acc[mi][ni][2], v3 = acc[mi][ni][3];
            if (MODE == 2) {
                int dest = col0 >> 8;
                int ccl = cc - dest * 256;
                if (dest < 2) {
                    __nv_bfloat16* dh = (dest == 0) ? q_hi : k_hi;
                    __nv_bfloat16* dl = (dest == 0) ? q_lo : k_lo;
                    __nv_bfloat16 h0 = __float2bfloat16(v0), h1 = __float2bfloat16(v1);
                    __nv_bfloat16 h2 = __float2bfloat16(v2), h3 = __float2bfloat16(v3);
                    *(__nv_bfloat162*)(dh + (size_t)rr * 256 + ccl)     = __nv_bfloat162(h0, h1);
                    *(__nv_bfloat162*)(dh + (size_t)(rr+8) * 256 + ccl) = __nv_bfloat162(h2, h3);
                    *(__nv_bfloat162*)(dl + (size_t)rr * 256 + ccl) = __nv_bfloat162(
                        __float2bfloat16(v0 - __bfloat162float(h0)),
                        __float2bfloat16(v1 - __bfloat162float(h1)));
                    *(__nv_bfloat162*)(dl + (size_t)(rr+8) * 256 + ccl) = __nv_bfloat162(
                        __float2bfloat16(v2 - __bfloat162float(h2)),
                        __float2bfloat16(v3 - __bfloat162float(h3)));
                } else {
                    *(float2*)&Cout[(size_t)rr * 256 + ccl]     = make_float2(v0, v1);
                    *(float2*)&Cout[(size_t)(rr+8) * 256 + ccl] = make_float2(v2, v3);
                }
            } else {
                if (BIAS) { v0 += bias[cc]; v1 += bias[cc+1]; v2 += bias[cc]; v3 += bias[cc+1]; }
                if (RES) {
                    const float2 r0v = *(const float2*)&res[(size_t)rr * N_ + cc];
                    const float2 r1v = *(const float2*)&res[(size_t)(rr+8) * N_ + cc];
                    v0 += r0v.x; v1 += r0v.y; v2 += r1v.x; v3 += r1v.y;
                }
                *(float2*)&Cout[(size_t)rr * N_ + cc]     = make_float2(v0, v1);
                *(float2*)&Cout[(size_t)(rr+8) * N_ + cc] = make_float2(v2, v3);
            }
        }
    }
}

// ---------------- energy via mma.sync (fp32 output) ----------------
#define ETILE 10240
__global__ void __launch_bounds__(256, 2)
energy_mma(const __nv_bfloat16* __restrict__ qhi, const __nv_bfloat16* __restrict__ qlo,
           const __nv_bfloat16* __restrict__ khi, const __nv_bfloat16* __restrict__ klo,
           float* __restrict__ E) {
    __shared__ __align__(16) char sb[4 * ETILE];
    const uint32_t sb32 = smem_u32(sb);
    const int nh = blockIdx.x;
    const int n = nh >> 3, h = nh & 7;
    const int t = threadIdx.x;
    const int lane = t & 31, warp = t >> 5;
    const int wm = warp & 1, wn = warp >> 1;

    const __nv_bfloat16* qh = qhi + ((size_t)(n * S) * H + h) * D;
    const __nv_bfloat16* ql = qlo + ((size_t)(n * S) * H + h) * D;
    const __nv_bfloat16* kh = khi + ((size_t)(n * S) * H + h) * D;
    const __nv_bfloat16* kl = klo + ((size_t)(n * S) * H + h) * D;

    #pragma unroll
    for (int i = 0; i < 2; i++) {
        int idx = t + i * 256;
        int r = idx >> 2, qq = idx & 3;
        size_t g = (size_t)r * (H * D) + qq * 8;
        uint32_t off = (uint32_t)(r * 80 + qq * 16);
        cp16(sb32 + off,             qh + g);
        cp16(sb32 + ETILE   + off,   ql + g);
        cp16(sb32 + 2*ETILE + off,   kh + g);
        cp16(sb32 + 3*ETILE + off,   kl + g);
    }
    cp_commit();
    cp_wait<0>();
    __syncthreads();

    float acc[4][4][4];
    #pragma unroll
    for (int mi = 0; mi < 4; mi++)
        #pragma unroll
        for (int ni = 0; ni < 4; ni++)
            #pragma unroll
            for (int x = 0; x < 4; x++) acc[mi][ni][x] = 0.f;

    #pragma unroll
    for (int kk = 0; kk < 2; kk++) {
        uint32_t bf[4][4];
        #pragma unroll
        for (int ni = 0; ni < 4; ni++) {
            int r = wn * 32 + ni * 8 + (lane & 7);
            int cbyte = (kk * 16 + ((lane >> 3) & 1) * 8) * 2;
            uint32_t addr = sb32 + 2*ETILE + r * 80 + cbyte + ((lane & 16) ? ETILE : 0);
            ldm_x4(bf[ni], addr);
        }
        #pragma unroll
        for (int mi = 0; mi < 4; mi++) {
            uint32_t ah[4], al[4];
            int r = wm * 64 + mi * 16 + (lane & 15);
            int cbyte = (kk * 16 + ((lane >> 4) << 3)) * 2;
            uint32_t addr = sb32 + r * 80 + cbyte;
            ldm_x4(ah, addr);
            ldm_x4(al, addr + ETILE);
            #pragma unroll
            for (int ni = 0; ni < 4; ni++) {
                mma_bf16(acc[mi][ni], ah, &bf[ni][0]);
                mma_bf16(acc[mi][ni], ah, &bf[ni][2]);
                mma_bf16(acc[mi][ni], al, &bf[ni][0]);
            }
        }
    }

    float* eb = E + (size_t)nh * SSQ;
    const int tr = lane >> 2, tc = (lane & 3) * 2;
    #pragma unroll
    for (int mi = 0; mi < 4; mi++)
        #pragma unroll
        for (int ni = 0; ni < 4; ni++) {
            int rr = wm * 64 + mi * 16 + tr;
            int cc = wn * 32 + ni * 8 + tc;
            *(float2*)&eb[(size_t)rr * S + cc]     = make_float2(acc[mi][ni][0], acc[mi][ni][1]);
            *(float2*)&eb[(size_t)(rr+8) * S + cc] = make_float2(acc[mi][ni][2], acc[mi][ni][3]);
        }
}

// ---------------- fused BN(affine) + softmax + AV, fp32 output --------------
#define SAV_SMEM (128*129*4 + 128*36*4)

typedef unsigned long long u64;
__device__ __forceinline__ u64 pack2(float x) {
    u64 r; unsigned u = __float_as_uint(x);
    asm("mov.b64 %0, {%1, %1};" : "=l"(r) : "r"(u));
    return r;
}
__device__ __forceinline__ void ffma2(u64& d, u64 a, u64 b) {
    asm("fma.rn.f32x2 %0, %1, %2, %0;" : "+l"(d) : "l"(a), "l"(b));
}
__device__ __forceinline__ float lo32(u64 v) { return __uint_as_float((unsigned)v); }
__device__ __forceinline__ float hi32(u64 v) { return __uint_as_float((unsigned)(v >> 32)); }

__global__ void __launch_bounds__(256, 2)
softmax_av(const float* __restrict__ E,
           const float* __restrict__ scpe, const float* __restrict__ shpe,
           const float* __restrict__ V, float* __restrict__ O) {
    extern __shared__ __align__(16) float smf[];
    float* attn = smf;
    float* vs   = smf + 128 * 129;
    const int nh = blockIdx.x;
    const int n = nh >> 3, h = nh & 7;
    const int t = threadIdx.x;
    const int lane = t & 31, warp = t >> 5;

    const float* vb = V + ((size_t)(n * S) * H + h) * D;
    #pragma unroll
    for (int i = 0; i < 4; i++) {
        int idx = t + i * 256;
        int l = idx >> 3, qq = idx & 7;
        *(float4*)&vs[l * 36 + qq * 4] = *(const float4*)&vb[(size_t)l * (H * D) + qq * 4];
    }

    const float* eb = E + (size_t)nh * SSQ;
    for (int rr = 0; rr < 16; rr++) {
        int row = warp * 16 + rr;
        const float* e = eb + (size_t)row * S;
        const float* sc = scpe + row * S;
        const float* sh = shpe + row * S;
        float v[4];
        float mx = -INFINITY;
        #pragma unroll
        for (int i = 0; i < 4; i++) {
            int ki = i * 32 + lane;
            v[i] = (e[ki] * sc[ki] + sh[ki]) * 0.0625f;
            mx = fmaxf(mx, v[i]);
        }
        #pragma unroll
        for (int off = 16; off > 0; off >>= 1)
            mx = fmaxf(mx, __shfl_xor_sync(0xffffffffu, mx, off));
        float sum = 0.f;
        #pragma unroll
        for (int i = 0; i < 4; i++) { v[i] = __expf(v[i] - mx); sum += v[i]; }
        #pragma unroll
        for (int off = 16; off > 0; off >>= 1)
            sum += __shfl_xor_sync(0xffffffffu, sum, off);
        float inv = 1.f / sum;
        #pragma unroll
        for (int i = 0; i < 4; i++)
            attn[row * 129 + i * 32 + lane] = v[i] * inv;
    }
    __syncthreads();

    const int ty = t >> 3, tx = t & 7;
    u64 acc[4][2];
    #pragma unroll
    for (int i = 0; i < 4; i++) { acc[i][0] = 0ull; acc[i][1] = 0ull; }
    for (int l = 0; l < 128; l++) {
        u64 b0 = *(const u64*)&vs[l * 36 + tx * 4];
        u64 b1 = *(const u64*)&vs[l * 36 + tx * 4 + 2];
        #pragma unroll
        for (int i = 0; i < 4; i++) {
            u64 ad = pack2(attn[(ty * 4 + i) * 129 + l]);
            ffma2(acc[i][0], ad, b0);
            ffma2(acc[i][1], ad, b1);
        }
    }
    #pragma unroll
    for (int i = 0; i < 4; i++) {
        int qrow = ty * 4 + i;
        size_t base = ((size_t)(n * S + qrow) * H + h) * D + tx * 4;
        *(float4*)&O[base] = make_float4(lo32(acc[i][0]), hi32(acc[i][0]),
                                         lo32(acc[i][1]), hi32(acc[i][1]));
    }
}

// ---------------------------------------------------------------------------
extern "C" void kernel_launch(void* const* d_in, const int* in_sizes, int n_in,
                              void* d_out, int out_size) {
    const float* x    = (const float*)d_in[0];
    const float* g_n  = (const float*)d_in[1];
    const float* b_n  = (const float*)d_in[2];
    const float* Wq   = (const float*)d_in[3];
    const float* Wk   = (const float*)d_in[4];
    const float* Wv   = (const float*)d_in[5];
    const float* Wo   = (const float*)d_in[6];
    const float* bo   = (const float*)d_in[7];
    const float* g_pe = (const float*)d_in[8];
    const float* b_pe = (const float*)d_in[9];
    const float* g0   = (const float*)d_in[10];
    const float* b0   = (const float*)d_in[11];
    const float* W0   = (const float*)d_in[12];
    const float* g1   = (const float*)d_in[13];
    const float* b1   = (const float*)d_in[14];
    const float* W1   = (const float*)d_in[15];
    float* out = (float*)d_out;

    float *v, *o, *e, *x1, *t2, *psum, *psq, *sc, *sh, *scpe, *shpe;
    __nv_bfloat16 *whi, *wlo, *qhi, *qlo, *khi, *klo;
    cudaGetSymbolAddress((void**)&v,    g_v);
    cudaGetSymbolAddress((void**)&o,    g_o);
    cudaGetSymbolAddress((void**)&e,    g_e);
    cudaGetSymbolAddress((void**)&x1,   g_x1);
    cudaGetSymbolAddress((void**)&t2,   g_t2);
    cudaGetSymbolAddress((void**)&psum, g_psum);
    cudaGetSymbolAddress((void**)&psq,  g_psq);
    cudaGetSymbolAddress((void**)&sc,   g_scale);
    cudaGetSymbolAddress((void**)&sh,   g_shift);
    cudaGetSymbolAddress((void**)&scpe, g_scale_pe);
    cudaGetSymbolAddress((void**)&shpe, g_shift_pe);
    cudaGetSymbolAddress((void**)&whi,  g_whi);
    cudaGetSymbolAddress((void**)&wlo,  g_wlo);
    cudaGetSymbolAddress((void**)&qhi,  g_qhi);
    cudaGetSymbolAddress((void**)&qlo,  g_qlo);
    cudaGetSymbolAddress((void**)&khi,  g_khi);
    cudaGetSymbolAddress((void**)&klo,  g_klo);

    cudaFuncSetAttribute(mma_gemm<2,true ,false,false,false>, cudaFuncAttributeMaxDynamicSharedMemorySize, MMA_SMEM);
    cudaFuncSetAttribute(mma_gemm<0,false,false,true ,true >, cudaFuncAttributeMaxDynamicSharedMemorySize, MMA_SMEM);
    cudaFuncSetAttribute(mma_gemm<0,true ,true ,false,false>, cudaFuncAttributeMaxDynamicSharedMemorySize, MMA_SMEM);
    cudaFuncSetAttribute(mma_gemm<0,true ,true ,false,true >, cudaFuncAttributeMaxDynamicSharedMemorySize, MMA_SMEM);
    cudaFuncSetAttribute(softmax_av, cudaFuncAttributeMaxDynamicSharedMemorySize, SAV_SMEM);

    // split all weights (one launch, no deps)
    splitW_all<<<512, 256>>>(Wq, Wk, Wv, Wo, W0, W1, whi, wlo);

    // BN over C on x
    bn_partial<<<dim3(1, 256), 256>>>(x, C, 128, psum, psq);
    bn_finalize_warp<<<C / 8, 256>>>(psum, psq, C, 256, 1.f / MROWS, g_n, b_n, sc, sh);

    // fused QKV GEMM (128-col tiles: tiles 0-1 -> q, 2-3 -> k, 4-5 -> v)
    dim3 gq(768 / 128, MROWS / 128);
    mma_gemm<2,true,false,false,false><<<gq, 256, MMA_SMEM>>>(x, sc, sh, whi, wlo,
        v, qhi, qlo, khi, klo, nullptr, nullptr, MROWS, 768, C);

    // energy (fp32 out)
    energy_mma<<<NHB, 256>>>(qhi, qlo, khi, klo, e);

    // BN over S*S on energy
    bn_partial<<<dim3(SSQ / 256, 8), 256>>>(e, SSQ, 256, psum, psq);
    bn_finalize<<<SSQ / 256, 256>>>(psum, psq, SSQ, 8, 1.f / NHB, g_pe, b_pe, scpe, shpe);

    // fused BN + softmax + AV -> fp32 o
    softmax_av<<<NHB, 256, SAV_SMEM>>>(e, scpe, shpe, v, o);

    // x1 = o @ Wo^T + bo + x
    dim3 go(C / 128, MROWS / 128);
    mma_gemm<0,false,false,true,true><<<go, 256, MMA_SMEM>>>(o, nullptr, nullptr,
        whi + WOFF_O, wlo + WOFF_O, x1, nullptr, nullptr, nullptr, nullptr, bo, x, MROWS, C, C);

    // FFN: BN0 stats, fused affine+relu inside FFN0 GEMM
    bn_partial<<<dim3(1, 256), 256>>>(x1, C, 128, psum, psq);
    bn_finalize_warp<<<C / 8, 256>>>(psum, psq, C, 256, 1.f / MROWS, g0, b0, sc, sh);
    dim3 gf0(C2 / 128, MROWS / 128);
    mma_gemm<0,true,true,false,false><<<gf0, 256, MMA_SMEM>>>(x1, sc, sh,
        whi + WOFF_0, wlo + WOFF_0, t2, nullptr, nullptr, nullptr, nullptr, nullptr, nullptr, MROWS, C2, C);

    // BN1 stats, fused affine+relu inside FFN1 GEMM, + x1
    bn_partial<<<dim3(2, 256), 256>>>(t2, C2, 128, psum, psq);
    bn_finalize_warp<<<C2 / 8, 256>>>(psum, psq, C2, 256, 1.f / MROWS, g1, b1, sc, sh);
    mma_gemm<0,true,true,false,true><<<go, 256, MMA_SMEM>>>(t2, sc, sh,
        whi + WOFF_1, wlo + WOFF_1, out, nullptr, nullptr, nullptr, nullptr, nullptr, x1, MROWS, C, C2);
}

// round 15
// speedup vs baseline: 1.0690x; 1.0204x over previous
#include <cuda_runtime.h>
#include <cuda_bf16.h>
#include <math.h>
#include <stdint.h>

// Problem constants
#define MB  256
#define S   128
#define C   256
#define H   8
#define D   32
#define MROWS (MB*S)           // 32768
#define C2  (2*C)              // 512
#define NHB (MB*H)             // 2048
#define SSQ (S*S)              // 16384

// weight offsets inside the packed split-weight buffer
#define WOFF_O   196608         // 768*256
#define WOFF_0   262144         // + 256*256
#define WOFF_1   393216         // + 512*256   (total 524288)

// ---------------- scratch (device globals) ----------------
__device__ float g_v [MROWS*C];
__device__ float g_o [MROWS*C];
__device__ float g_e [NHB*SSQ];
__device__ float g_x1[MROWS*C];
__device__ float g_t2[MROWS*C2];
__device__ float g_psum[262144];
__device__ float g_psq [262144];
__device__ float g_scale[C2];
__device__ float g_shift[C2];
__device__ float g_scale_pe[SSQ];
__device__ float g_shift_pe[SSQ];
__device__ __nv_bfloat16 g_whi[524288];
__device__ __nv_bfloat16 g_wlo[524288];
__device__ __nv_bfloat16 g_qhi[MROWS*C];
__device__ __nv_bfloat16 g_qlo[MROWS*C];
__device__ __nv_bfloat16 g_khi[MROWS*C];
__device__ __nv_bfloat16 g_klo[MROWS*C];

// ---------------- BN stats: deterministic 2-stage reduction ----------------
__global__ void bn_partial(const float* __restrict__ X, int Cdim, int rowsPerBlock,
                           float* __restrict__ psum, float* __restrict__ psq) {
    int c = blockIdx.x * blockDim.x + threadIdx.x;
    int r0 = blockIdx.y * rowsPerBlock;
    float s = 0.f, q = 0.f;
    const float* Xp = X + (size_t)r0 * Cdim + c;
    for (int i = 0; i < rowsPerBlock; i++) {
        float v = Xp[(size_t)i * Cdim];
        s += v; q += v * v;
    }
    psum[(size_t)blockIdx.y * Cdim + c] = s;
    psq [(size_t)blockIdx.y * Cdim + c] = q;
}

// per-thread finalize (energy BN: many channels, few parts)
__global__ void bn_finalize(const float* __restrict__ psum, const float* __restrict__ psq,
                            int Cdim, int nparts, float invM,
                            const float* __restrict__ g, const float* __restrict__ b,
                            float* __restrict__ scale, float* __restrict__ shift) {
    int c = blockIdx.x * blockDim.x + threadIdx.x;
    float s = 0.f, q = 0.f;
    for (int p = 0; p < nparts; p++) {
        s += psum[(size_t)p * Cdim + c];
        q += psq [(size_t)p * Cdim + c];
    }
    float mean = s * invM;
    float var  = q * invM - mean * mean;
    float sc   = g[c] * rsqrtf(var + 1e-5f);
    scale[c] = sc;
    shift[c] = b[c] - mean * sc;
}

// warp-per-channel finalize (few channels, many parts)
__global__ void bn_finalize_warp(const float* __restrict__ psum, const float* __restrict__ psq,
                                 int Cdim, int nparts, float invM,
                                 const float* __restrict__ g, const float* __restrict__ b,
                                 float* __restrict__ scale, float* __restrict__ shift) {
    int warp = threadIdx.x >> 5, lane = threadIdx.x & 31;
    int c = blockIdx.x * 8 + warp;
    float s = 0.f, q = 0.f;
    for (int p = lane; p < nparts; p += 32) {
        s += psum[(size_t)p * Cdim + c];
        q += psq [(size_t)p * Cdim + c];
    }
    #pragma unroll
    for (int off = 16; off > 0; off >>= 1) {
        s += __shfl_xor_sync(0xffffffffu, s, off);
        q += __shfl_xor_sync(0xffffffffu, q, off);
    }
    if (lane == 0) {
        float mean = s * invM;
        float var  = q * invM - mean * mean;
        float sc   = g[c] * rsqrtf(var + 1e-5f);
        scale[c] = sc;
        shift[c] = b[c] - mean * sc;
    }
}

// ---------------- split helpers ----------------
__device__ __forceinline__ void split4(float4 v, __nv_bfloat16* hi, __nv_bfloat16* lo,
                                       size_t off) {
    __nv_bfloat16 h0 = __float2bfloat16(v.x), h1 = __float2bfloat16(v.y);
    __nv_bfloat16 h2 = __float2bfloat16(v.z), h3 = __float2bfloat16(v.w);
    *(__nv_bfloat162*)(hi + off)     = __nv_bfloat162(h0, h1);
    *(__nv_bfloat162*)(hi + off + 2) = __nv_bfloat162(h2, h3);
    *(__nv_bfloat162*)(lo + off) = __nv_bfloat162(
        __float2bfloat16(v.x - __bfloat162float(h0)),
        __float2bfloat16(v.y - __bfloat162float(h1)));
    *(__nv_bfloat162*)(lo + off + 2) = __nv_bfloat162(
        __float2bfloat16(v.z - __bfloat162float(h2)),
        __float2bfloat16(v.w - __bfloat162float(h3)));
}

__global__ void splitW_all(const float* __restrict__ Wq, const float* __restrict__ Wk,
                           const float* __restrict__ Wv, const float* __restrict__ Wo,
                           const float* __restrict__ W0, const float* __restrict__ W1,
                           __nv_bfloat16* __restrict__ hi, __nv_bfloat16* __restrict__ lo) {
    int i = blockIdx.x * blockDim.x + threadIdx.x;    // 0..131071
    const float* src; int local;
    if (i < 16384)       { src = Wq; local = i; }
    else if (i < 32768)  { src = Wk; local = i - 16384; }
    else if (i < 49152)  { src = Wv; local = i - 32768; }
    else if (i < 65536)  { src = Wo; local = i - 49152; }
    else if (i < 98304)  { src = W0; local = i - 65536; }
    else                 { src = W1; local = i - 98304; }
    split4(((const float4*)src)[local], hi, lo, (size_t)i * 4);
}

// ---------------- mma.sync / cp.async helpers ----------------
__device__ __forceinline__ uint32_t smem_u32(const void* p) {
    uint32_t a;
    asm("{ .reg .u64 t; cvta.to.shared.u64 t, %1; cvt.u32.u64 %0, t; }" : "=r"(a) : "l"(p));
    return a;
}
__device__ __forceinline__ void ldm_x4(uint32_t* r, uint32_t addr) {
    asm volatile("ldmatrix.sync.aligned.m8n8.x4.shared.b16 {%0,%1,%2,%3}, [%4];"
                 : "=r"(r[0]), "=r"(r[1]), "=r"(r[2]), "=r"(r[3]) : "r"(addr));
}
__device__ __forceinline__ void ldm_x2(uint32_t* r, uint32_t addr) {
    asm volatile("ldmatrix.sync.aligned.m8n8.x2.shared.b16 {%0,%1}, [%2];"
                 : "=r"(r[0]), "=r"(r[1]) : "r"(addr));
}
__device__ __forceinline__ void mma_bf16(float* c, const uint32_t* a, const uint32_t* b) {
    asm volatile(
        "mma.sync.aligned.m16n8k16.row.col.f32.bf16.bf16.f32 "
        "{%0,%1,%2,%3}, {%4,%5,%6,%7}, {%8,%9}, {%0,%1,%2,%3};"
        : "+f"(c[0]), "+f"(c[1]), "+f"(c[2]), "+f"(c[3])
        : "r"(a[0]), "r"(a[1]), "r"(a[2]), "r"(a[3]), "r"(b[0]), "r"(b[1]));
}
__device__ __forceinline__ void cp16(uint32_t dst, const void* src) {
    asm volatile("cp.async.cg.shared.global [%0], [%1], 16;" :: "r"(dst), "l"(src));
}
__device__ __forceinline__ void cp_commit() {
    asm volatile("cp.async.commit_group;" ::: "memory");
}
template<int N> __device__ __forceinline__ void cp_wait() {
    asm volatile("cp.async.wait_group %0;" :: "n"(N) : "memory");
}

// ---------------- fused split-bf16 GEMM, 128x128 tile, 1-barrier pipeline ---
// Cout[M,N] = split(op(A_f32))[M,K] @ (Bh+Bl)[N,K]^T  (+ bias, + residual)
// 8 warps 2M x 4N (warp 64x32), K-chunk 32.
// A: 2 stages (LDG->regs->affine/split->STS). B: 3 stages (cp.async).
// SMEM: [A: 2 x 20480][B: 3 x 20480][scales 4096] = 106496 B, 2 CTAs/SM.
#define ASTAGE 20480
#define BSTAGE 20480
#define AHALF  10240
#define B_BASE (2*ASTAGE)
#define SC_OFF (2*ASTAGE + 3*BSTAGE)
#define MMA_SMEM (SC_OFF + 4096)

template<int MODE, bool AFFINE, bool RELU, bool BIAS, bool RES>
__global__ void __launch_bounds__(256, 2)
mma_gemm(const float* __restrict__ A,
         const float* __restrict__ scale, const float* __restrict__ shift,
         const __nv_bfloat16* __restrict__ b_hi, const __nv_bfloat16* __restrict__ b_lo,
         float* __restrict__ Cout,
         __nv_bfloat16* __restrict__ q_hi, __nv_bfloat16* __restrict__ q_lo,
         __nv_bfloat16* __restrict__ k_hi, __nv_bfloat16* __restrict__ k_lo,
         const float* __restrict__ bias, const float* __restrict__ res,
         int M_, int N_, int K_) {
    extern __shared__ __align__(16) char sb[];
    const uint32_t sb32 = smem_u32(sb);
    float* sSc = (float*)(sb + SC_OFF);
    float* sSh = (float*)(sb + SC_OFF + 2048);

    const int t = threadIdx.x;
    const int lane = t & 31, warp = t >> 5;
    const int wm = warp & 1, wn = warp >> 1;
    const int row0 = blockIdx.y * 128, col0 = blockIdx.x * 128;

    if (AFFINE) {
        for (int i = t; i < K_; i += 256) { sSc[i] = scale[i]; sSh[i] = shift[i]; }
    }

    float acc[4][4][4];
    #pragma unroll
    for (int mi = 0; mi < 4; mi++)
        #pragma unroll
        for (int ni = 0; ni < 4; ni++)
            #pragma unroll
            for (int x = 0; x < 4; x++) acc[mi][ni][x] = 0.f;

    float4 aR[4];
    auto ldgA = [&](int k0) {
        #pragma unroll
        for (int i = 0; i < 4; i++) {
            int idx = t + i * 256;
            int r = idx >> 3, q = idx & 7;
            aR[i] = *(const float4*)&A[(size_t)(row0 + r) * K_ + k0 + q * 4];
        }
    };
    auto stsA = [&](int s, int k0) {
        char* base = sb + s * ASTAGE;
        #pragma unroll
        for (int i = 0; i < 4; i++) {
            int idx = t + i * 256;
            int r = idx >> 3, q = idx & 7;
            float4 v = aR[i];
            if (AFFINE) {
                int kc = k0 + q * 4;
                v.x = v.x * sSc[kc+0] + sSh[kc+0];
                v.y = v.y * sSc[kc+1] + sSh[kc+1];
                v.z = v.z * sSc[kc+2] + sSh[kc+2];
                v.w = v.w * sSc[kc+3] + sSh[kc+3];
                if (RELU) {
                    v.x = fmaxf(v.x, 0.f); v.y = fmaxf(v.y, 0.f);
                    v.z = fmaxf(v.z, 0.f); v.w = fmaxf(v.w, 0.f);
                }
            }
            __nv_bfloat16 h0 = __float2bfloat16(v.x), h1 = __float2bfloat16(v.y);
            __nv_bfloat16 h2 = __float2bfloat16(v.z), h3 = __float2bfloat16(v.w);
            __nv_bfloat162 hA(h0, h1), hB(h2, h3);
            __nv_bfloat162 lA(__float2bfloat16(v.x - __bfloat162float(h0)),
                              __float2bfloat16(v.y - __bfloat162float(h1)));
            __nv_bfloat162 lB(__float2bfloat16(v.z - __bfloat162float(h2)),
                              __float2bfloat16(v.w - __bfloat162float(h3)));
            int off = r * 80 + q * 8;
            *(__nv_bfloat162*)(base + off)             = hA;
            *(__nv_bfloat162*)(base + off + 4)         = hB;
            *(__nv_bfloat162*)(base + AHALF + off)     = lA;
            *(__nv_bfloat162*)(base + AHALF + off + 4) = lB;
        }
    };
    auto cpB = [&](int s, int k0) {
        uint32_t base = sb32 + B_BASE + s * BSTAGE;
        #pragma unroll
        for (int i = 0; i < 2; i++) {
            int idx = t + i * 256;
            int r = idx >> 2, qq = idx & 3;
            uint32_t off = (uint32_t)(r * 80 + qq * 16);
            size_t gb = (size_t)(col0 + r) * K_ + k0 + qq * 8;
            cp16(base + off,         b_hi + gb);
            cp16(base + AHALF + off, b_lo + gb);
        }
        cp_commit();
    };
    auto compute = [&](int sa, int sbuf) {
        uint32_t abase = sb32 + sa * ASTAGE;
        uint32_t bbase = sb32 + B_BASE + sbuf * BSTAGE;
        #pragma unroll
        for (int kk = 0; kk < 2; kk++) {
            uint32_t bh[4][2], bl[4][2];
            #pragma unroll
            for (int ni = 0; ni < 4; ni++) {
                int r = wn * 32 + ni * 8 + (lane & 7);
                int cbyte = (kk * 16 + ((lane >> 3) & 1) * 8) * 2;
                uint32_t addr = bbase + r * 80 + cbyte;
                ldm_x2(bh[ni], addr);
                ldm_x2(bl[ni], addr + AHALF);
            }
            #pragma unroll
            for (int mi = 0; mi < 4; mi++) {
                uint32_t ah[4], al[4];
                int r = wm * 64 + mi * 16 + (lane & 15);
                int cbyte = (kk * 16 + ((lane >> 4) << 3)) * 2;
                uint32_t addr = abase + r * 80 + cbyte;
                ldm_x4(ah, addr);
                ldm_x4(al, addr + AHALF);
                #pragma unroll
                for (int ni = 0; ni < 4; ni++) {
                    mma_bf16(acc[mi][ni], ah, bh[ni]);
                    mma_bf16(acc[mi][ni], ah, bl[ni]);
                    mma_bf16(acc[mi][ni], al, bh[ni]);
                }
            }
        }
    };

    const int nchunk = K_ >> 5;
    ldgA(0);
    cpB(0, 0);
    if (nchunk > 1) cpB(1, 32);
    __syncthreads();                  // scales visible for stsA
    stsA(0, 0);
    if (nchunk > 1) ldgA(32);

    for (int ch = 0; ch < nchunk; ch++) {
        if (ch + 1 < nchunk) cp_wait<1>(); else cp_wait<0>();
        __syncthreads();
        if (ch + 1 < nchunk) stsA((ch + 1) & 1, (ch + 1) * 32);
        compute(ch & 1, ch % 3);
        if (ch + 2 < nchunk) {
            ldgA((ch + 2) * 32);
            cpB((ch + 2) % 3, (ch + 2) * 32);
        }
    }

    // ---- epilogue ----
    const int tr = lane >> 2, tc = (lane & 3) * 2;
    #pragma unroll
    for (int mi = 0; mi < 4; mi++) {
        #pragma unroll
        for (int ni = 0; ni < 4; ni++) {
            int rr = row0 + wm * 64 + mi * 16 + tr;
            int cc = col0 + wn * 32 + ni * 8 + tc;
            float v0 = acc[mi][ni][0], v1 = acc[mi][ni][1];
            float v2 = acc[mi][ni][2], v3 = acc[mi][ni][3];
            if (MODE == 2) {
                int dest = col0 >> 8;
                int ccl = cc - dest * 256;
                if (dest < 2) {
                    __nv_bfloat16* dh = (dest == 0) ? q_hi : k_hi;
                    __nv_bfloat16* dl = (dest == 0) ? q_lo : k_lo;
                    __nv_bfloat16 h0 = __float2bfloat16(v0), h1 = __float2bfloat16(v1);
                    __nv_bfloat16 h2 = __float2bfloat16(v2), h3 = __float2bfloat16(v3);
                    *(__nv_bfloat162*)(dh + (size_t)rr * 256 + ccl)     = __nv_bfloat162(h0, h1);
                    *(__nv_bfloat162*)(dh + (size_t)(rr+8) * 256 + ccl) = __nv_bfloat162(h2, h3);
                    *(__nv_bfloat162*)(dl + (size_t)rr * 256 + ccl) = __nv_bfloat162(
                        __float2bfloat16(v0 - __bfloat162float(h0)),
                        __float2bfloat16(v1 - __bfloat162float(h1)));
                    *(__nv_bfloat162*)(dl + (size_t)(rr+8) * 256 + ccl) = __nv_bfloat162(
                        __float2bfloat16(v2 - __bfloat162float(h2)),
                        __float2bfloat16(v3 - __bfloat162float(h3)));
                } else {
                    *(float2*)&Cout[(size_t)rr * 256 + ccl]     = make_float2(v0, v1);
                    *(float2*)&Cout[(size_t)(rr+8) * 256 + ccl] = make_float2(v2, v3);
                }
            } else {
                if (BIAS) { v0 += bias[cc]; v1 += bias[cc+1]; v2 += bias[cc]; v3 += bias[cc+1]; }
                if (RES) {
                    const float2 r0v = *(const float2*)&res[(size_t)rr * N_ + cc];
                    const float2 r1v = *(const float2*)&res[(size_t)(rr+8) * N_ + cc];
                    v0 += r0v.x; v1 += r0v.y; v2 += r1v.x; v3 += r1v.y;
                }
                *(float2*)&Cout[(size_t)rr * N_ + cc]     = make_float2(v0, v1);
                *(float2*)&Cout[(size_t)(rr+8) * N_ + cc] = make_float2(v2, v3);
            }
        }
    }
}

// ---------------- energy via mma.sync (fp32 output) ----------------
#define ETILE 10240
__global__ void __launch_bounds__(256, 2)
energy_mma(const __nv_bfloat16* __restrict__ qhi, const __nv_bfloat16* __restrict__ qlo,
           const __nv_bfloat16* __restrict__ khi, const __nv_bfloat16* __restrict__ klo,
           float* __restrict__ E) {
    __shared__ __align__(16) char sb[4 * ETILE];
    const uint32_t sb32 = smem_u32(sb);
    const int nh = blockIdx.x;
    const int n = nh >> 3, h = nh & 7;
    const int t = threadIdx.x;
    const int lane = t & 31, warp = t >> 5;
    const int wm = warp & 1, wn = warp >> 1;

    const __nv_bfloat16* qh = qhi + ((size_t)(n * S) * H + h) * D;
    const __nv_bfloat16* ql = qlo + ((size_t)(n * S) * H + h) * D;
    const __nv_bfloat16* kh = khi + ((size_t)(n * S) * H + h) * D;
    const __nv_bfloat16* kl = klo + ((size_t)(n * S) * H + h) * D;

    #pragma unroll
    for (int i = 0; i < 2; i++) {
        int idx = t + i * 256;
        int r = idx >> 2, qq = idx & 3;
        size_t g = (size_t)r * (H * D) + qq * 8;
        uint32_t off = (uint32_t)(r * 80 + qq * 16);
        cp16(sb32 + off,             qh + g);
        cp16(sb32 + ETILE   + off,   ql + g);
        cp16(sb32 + 2*ETILE + off,   kh + g);
        cp16(sb32 + 3*ETILE + off,   kl + g);
    }
    cp_commit();
    cp_wait<0>();
    __syncthreads();

    float acc[4][4][4];
    #pragma unroll
    for (int mi = 0; mi < 4; mi++)
        #pragma unroll
        for (int ni = 0; ni < 4; ni++)
            #pragma unroll
            for (int x = 0; x < 4; x++) acc[mi][ni][x] = 0.f;

    #pragma unroll
    for (int kk = 0; kk < 2; kk++) {
        uint32_t bh[4][2], bl[4][2];
        #pragma unroll
        for (int ni = 0; ni < 4; ni++) {
            int r = wn * 32 + ni * 8 + (lane & 7);
            int cbyte = (kk * 16 + ((lane >> 3) & 1) * 8) * 2;
            uint32_t addr = sb32 + 2*ETILE + r * 80 + cbyte;
            ldm_x2(bh[ni], addr);
            ldm_x2(bl[ni], addr + ETILE);
        }
        #pragma unroll
        for (int mi = 0; mi < 4; mi++) {
            uint32_t ah[4], al[4];
            int r = wm * 64 + mi * 16 + (lane & 15);
            int cbyte = (kk * 16 + ((lane >> 4) << 3)) * 2;
            uint32_t addr = sb32 + r * 80 + cbyte;
            ldm_x4(ah, addr);
            ldm_x4(al, addr + ETILE);
            #pragma unroll
            for (int ni = 0; ni < 4; ni++) {
                mma_bf16(acc[mi][ni], ah, bh[ni]);
                mma_bf16(acc[mi][ni], ah, bl[ni]);
                mma_bf16(acc[mi][ni], al, bh[ni]);
            }
        }
    }

    float* eb = E + (size_t)nh * SSQ;
    const int tr = lane >> 2, tc = (lane & 3) * 2;
    #pragma unroll
    for (int mi = 0; mi < 4; mi++)
        #pragma unroll
        for (int ni = 0; ni < 4; ni++) {
            int rr = wm * 64 + mi * 16 + tr;
            int cc = wn * 32 + ni * 8 + tc;
            *(float2*)&eb[(size_t)rr * S + cc]     = make_float2(acc[mi][ni][0], acc[mi][ni][1]);
            *(float2*)&eb[(size_t)(rr+8) * S + cc] = make_float2(acc[mi][ni][2], acc[mi][ni][3]);
        }
}

// ---------------- fused BN(affine) + softmax + AV, fp32 output --------------
#define SAV_SMEM (128*129*4 + 128*36*4)

typedef unsigned long long u64;
__device__ __forceinline__ u64 pack2(float x) {
    u64 r; unsigned u = __float_as_uint(x);
    asm("mov.b64 %0, {%1, %1};" : "=l"(r) : "r"(u));
    return r;
}
__device__ __forceinline__ void ffma2(u64& d, u64 a, u64 b) {
    asm("fma.rn.f32x2 %0, %1, %2, %0;" : "+l"(d) : "l"(a), "l"(b));
}
__device__ __forceinline__ float lo32(u64 v) { return __uint_as_float((unsigned)v); }
__device__ __forceinline__ float hi32(u64 v) { return __uint_as_float((unsigned)(v >> 32)); }

__global__ void __launch_bounds__(256, 2)
softmax_av(const float* __restrict__ E,
           const float* __restrict__ scpe, const float* __restrict__ shpe,
           const float* __restrict__ V, float* __restrict__ O) {
    extern __shared__ __align__(16) float smf[];
    float* attn = smf;
    float* vs   = smf + 128 * 129;
    const int nh = blockIdx.x;
    const int n = nh >> 3, h = nh & 7;
    const int t = threadIdx.x;
    const int lane = t & 31, warp = t >> 5;

    const float* vb = V + ((size_t)(n * S) * H + h) * D;
    #pragma unroll
    for (int i = 0; i < 4; i++) {
        int idx = t + i * 256;
        int l = idx >> 3, qq = idx & 7;
        *(float4*)&vs[l * 36 + qq * 4] = *(const float4*)&vb[(size_t)l * (H * D) + qq * 4];
    }

    const float* eb = E + (size_t)nh * SSQ;
    for (int rr = 0; rr < 16; rr++) {
        int row = warp * 16 + rr;
        const float* e = eb + (size_t)row * S;
        const float* sc = scpe + row * S;
        const float* sh = shpe + row * S;
        float v[4];
        float mx = -INFINITY;
        #pragma unroll
        for (int i = 0; i < 4; i++) {
            int ki = i * 32 + lane;
            v[i] = (e[ki] * sc[ki] + sh[ki]) * 0.0625f;
            mx = fmaxf(mx, v[i]);
        }
        #pragma unroll
        for (int off = 16; off > 0; off >>= 1)
            mx = fmaxf(mx, __shfl_xor_sync(0xffffffffu, mx, off));
        float sum = 0.f;
        #pragma unroll
        for (int i = 0; i < 4; i++) { v[i] = __expf(v[i] - mx); sum += v[i]; }
        #pragma unroll
        for (int off = 16; off > 0; off >>= 1)
            sum += __shfl_xor_sync(0xffffffffu, sum, off);
        float inv = 1.f / sum;
        #pragma unroll
        for (int i = 0; i < 4; i++)
            attn[row * 129 + i * 32 + lane] = v[i] * inv;
    }
    __syncthreads();

    const int ty = t >> 3, tx = t & 7;
    u64 acc[4][2];
    #pragma unroll
    for (int i = 0; i < 4; i++) { acc[i][0] = 0ull; acc[i][1] = 0ull; }
    for (int l = 0; l < 128; l++) {
        u64 b0 = *(const u64*)&vs[l * 36 + tx * 4];
        u64 b1 = *(const u64*)&vs[l * 36 + tx * 4 + 2];
        #pragma unroll
        for (int i = 0; i < 4; i++) {
            u64 ad = pack2(attn[(ty * 4 + i) * 129 + l]);
            ffma2(acc[i][0], ad, b0);
            ffma2(acc[i][1], ad, b1);
        }
    }
    #pragma unroll
    for (int i = 0; i < 4; i++) {
        int qrow = ty * 4 + i;
        size_t base = ((size_t)(n * S + qrow) * H + h) * D + tx * 4;
        *(float4*)&O[base] = make_float4(lo32(acc[i][0]), hi32(acc[i][0]),
                                         lo32(acc[i][1]), hi32(acc[i][1]));
    }
}

// ---------------------------------------------------------------------------
extern "C" void kernel_launch(void* const* d_in, const int* in_sizes, int n_in,
                              void* d_out, int out_size) {
    const float* x    = (const float*)d_in[0];
    const float* g_n  = (const float*)d_in[1];
    const float* b_n  = (const float*)d_in[2];
    const float* Wq   = (const float*)d_in[3];
    const float* Wk   = (const float*)d_in[4];
    const float* Wv   = (const float*)d_in[5];
    const float* Wo   = (const float*)d_in[6];
    const float* bo   = (const float*)d_in[7];
    const float* g_pe = (const float*)d_in[8];
    const float* b_pe = (const float*)d_in[9];
    const float* g0   = (const float*)d_in[10];
    const float* b0   = (const float*)d_in[11];
    const float* W0   = (const float*)d_in[12];
    const float* g1   = (const float*)d_in[13];
    const float* b1   = (const float*)d_in[14];
    const float* W1   = (const float*)d_in[15];
    float* out = (float*)d_out;

    float *v, *o, *e, *x1, *t2, *psum, *psq, *sc, *sh, *scpe, *shpe;
    __nv_bfloat16 *whi, *wlo, *qhi, *qlo, *khi, *klo;
    cudaGetSymbolAddress((void**)&v,    g_v);
    cudaGetSymbolAddress((void**)&o,    g_o);
    cudaGetSymbolAddress((void**)&e,    g_e);
    cudaGetSymbolAddress((void**)&x1,   g_x1);
    cudaGetSymbolAddress((void**)&t2,   g_t2);
    cudaGetSymbolAddress((void**)&psum, g_psum);
    cudaGetSymbolAddress((void**)&psq,  g_psq);
    cudaGetSymbolAddress((void**)&sc,   g_scale);
    cudaGetSymbolAddress((void**)&sh,   g_shift);
    cudaGetSymbolAddress((void**)&scpe, g_scale_pe);
    cudaGetSymbolAddress((void**)&shpe, g_shift_pe);
    cudaGetSymbolAddress((void**)&whi,  g_whi);
    cudaGetSymbolAddress((void**)&wlo,  g_wlo);
    cudaGetSymbolAddress((void**)&qhi,  g_qhi);
    cudaGetSymbolAddress((void**)&qlo,  g_qlo);
    cudaGetSymbolAddress((void**)&khi,  g_khi);
    cudaGetSymbolAddress((void**)&klo,  g_klo);

    cudaFuncSetAttribute(mma_gemm<2,true ,false,false,false>, cudaFuncAttributeMaxDynamicSharedMemorySize, MMA_SMEM);
    cudaFuncSetAttribute(mma_gemm<0,false,false,true ,true >, cudaFuncAttributeMaxDynamicSharedMemorySize, MMA_SMEM);
    cudaFuncSetAttribute(mma_gemm<0,true ,true ,false,false>, cudaFuncAttributeMaxDynamicSharedMemorySize, MMA_SMEM);
    cudaFuncSetAttribute(mma_gemm<0,true ,true ,false,true >, cudaFuncAttributeMaxDynamicSharedMemorySize, MMA_SMEM);
    cudaFuncSetAttribute(softmax_av, cudaFuncAttributeMaxDynamicSharedMemorySize, SAV_SMEM);

    // split all weights (one launch, no deps)
    splitW_all<<<512, 256>>>(Wq, Wk, Wv, Wo, W0, W1, whi, wlo);

    // BN over C on x
    bn_partial<<<dim3(1, 256), 256>>>(x, C, 128, psum, psq);
    bn_finalize_warp<<<C / 8, 256>>>(psum, psq, C, 256, 1.f / MROWS, g_n, b_n, sc, sh);

    // fused QKV GEMM (128-col tiles: tiles 0-1 -> q, 2-3 -> k, 4-5 -> v)
    dim3 gq(768 / 128, MROWS / 128);
    mma_gemm<2,true,false,false,false><<<gq, 256, MMA_SMEM>>>(x, sc, sh, whi, wlo,
        v, qhi, qlo, khi, klo, nullptr, nullptr, MROWS, 768, C);

    // energy (fp32 out)
    energy_mma<<<NHB, 256>>>(qhi, qlo, khi, klo, e);

    // BN over S*S on energy (16 partials for more parallelism)
    bn_partial<<<dim3(SSQ / 256, 16), 256>>>(e, SSQ, 128, psum, psq);
    bn_finalize<<<SSQ / 256, 256>>>(psum, psq, SSQ, 16, 1.f / NHB, g_pe, b_pe, scpe, shpe);

    // fused BN + softmax + AV -> fp32 o
    softmax_av<<<NHB, 256, SAV_SMEM>>>(e, scpe, shpe, v, o);

    // x1 = o @ Wo^T + bo + x
    dim3 go(C / 128, MROWS / 128);
    mma_gemm<0,false,false,true,true><<<go, 256, MMA_SMEM>>>(o, nullptr, nullptr,
        whi + WOFF_O, wlo + WOFF_O, x1, nullptr, nullptr, nullptr, nullptr, bo, x, MROWS, C, C);

    // FFN: BN0 stats, fused affine+relu inside FFN0 GEMM
    bn_partial<<<dim3(1, 256), 256>>>(x1, C, 128, psum, psq);
    bn_finalize_warp<<<C / 8, 256>>>(psum, psq, C, 256, 1.f / MROWS, g0, b0, sc, sh);
    dim3 gf0(C2 / 128, MROWS / 128);
    mma_gemm<0,true,true,false,false><<<gf0, 256, MMA_SMEM>>>(x1, sc, sh,
        whi + WOFF_0, wlo + WOFF_0, t2, nullptr, nullptr, nullptr, nullptr, nullptr, nullptr, MROWS, C2, C);

    // BN1 stats, fused affine+relu inside FFN1 GEMM, + x1
    bn_partial<<<dim3(2, 256), 256>>>(t2, C2, 128, psum, psq);
    bn_finalize_warp<<<C2 / 8, 256>>>(psum, psq, C2, 256, 1.f / MROWS, g1, b1, sc, sh);
    mma_gemm<0,true,true,false,true><<<go, 256, MMA_SMEM>>>(t2, sc, sh,
        whi + WOFF_1, wlo + WOFF_1, out, nullptr, nullptr, nullptr, nullptr, nullptr, x1, MROWS, C, C2);
}

// round 16
// speedup vs baseline: 1.1069x; 1.0355x over previous
#include <cuda_runtime.h>
#include <cuda_bf16.h>
#include <math.h>
#include <stdint.h>

// Problem constants
#define MB  256
#define S   128
#define C   256
#define H   8
#define D   32
#define MROWS (MB*S)           // 32768
#define C2  (2*C)              // 512
#define NHB (MB*H)             // 2048
#define SSQ (S*S)              // 16384

// weight offsets inside the packed split-weight buffer
#define WOFF_O   196608         // 768*256
#define WOFF_0   262144         // + 256*256
#define WOFF_1   393216         // + 512*256   (total 524288)

// ---------------- scratch (device globals) ----------------
__device__ float g_v [MROWS*C];
__device__ float g_o [MROWS*C];
__device__ float g_e [NHB*SSQ];
__device__ float g_x1[MROWS*C];
__device__ float g_t2[MROWS*C2];
__device__ float g_psum[262144];
__device__ float g_psq [262144];
__device__ float g_scale[C2];
__device__ float g_shift[C2];
__device__ float g_scale_pe[SSQ];
__device__ float g_shift_pe[SSQ];
__device__ __nv_bfloat16 g_whi[524288];
__device__ __nv_bfloat16 g_wlo[524288];
__device__ __nv_bfloat16 g_qhi[MROWS*C];
__device__ __nv_bfloat16 g_qlo[MROWS*C];
__device__ __nv_bfloat16 g_khi[MROWS*C];
__device__ __nv_bfloat16 g_klo[MROWS*C];

// ---------------- BN stats: deterministic 2-stage reduction ----------------
__global__ void bn_partial(const float* __restrict__ X, int Cdim, int rowsPerBlock,
                           float* __restrict__ psum, float* __restrict__ psq) {
    int c = blockIdx.x * blockDim.x + threadIdx.x;
    int r0 = blockIdx.y * rowsPerBlock;
    float s = 0.f, q = 0.f;
    const float* Xp = X + (size_t)r0 * Cdim + c;
    for (int i = 0; i < rowsPerBlock; i++) {
        float v = Xp[(size_t)i * Cdim];
        s += v; q += v * v;
    }
    psum[(size_t)blockIdx.y * Cdim + c] = s;
    psq [(size_t)blockIdx.y * Cdim + c] = q;
}

// per-thread finalize (energy BN: many channels, few parts)
__global__ void bn_finalize(const float* __restrict__ psum, const float* __restrict__ psq,
                            int Cdim, int nparts, float invM,
                            const float* __restrict__ g, const float* __restrict__ b,
                            float* __restrict__ scale, float* __restrict__ shift) {
    int c = blockIdx.x * blockDim.x + threadIdx.x;
    float s = 0.f, q = 0.f;
    for (int p = 0; p < nparts; p++) {
        s += psum[(size_t)p * Cdim + c];
        q += psq [(size_t)p * Cdim + c];
    }
    float mean = s * invM;
    float var  = q * invM - mean * mean;
    float sc   = g[c] * rsqrtf(var + 1e-5f);
    scale[c] = sc;
    shift[c] = b[c] - mean * sc;
}

// warp-per-channel finalize (few channels, many parts)
__global__ void bn_finalize_warp(const float* __restrict__ psum, const float* __restrict__ psq,
                                 int Cdim, int nparts, float invM,
                                 const float* __restrict__ g, const float* __restrict__ b,
                                 float* __restrict__ scale, float* __restrict__ shift) {
    int warp = threadIdx.x >> 5, lane = threadIdx.x & 31;
    int c = blockIdx.x * 8 + warp;
    float s = 0.f, q = 0.f;
    for (int p = lane; p < nparts; p += 32) {
        s += psum[(size_t)p * Cdim + c];
        q += psq [(size_t)p * Cdim + c];
    }
    #pragma unroll
    for (int off = 16; off > 0; off >>= 1) {
        s += __shfl_xor_sync(0xffffffffu, s, off);
        q += __shfl_xor_sync(0xffffffffu, q, off);
    }
    if (lane == 0) {
        float mean = s * invM;
        float var  = q * invM - mean * mean;
        float sc   = g[c] * rsqrtf(var + 1e-5f);
        scale[c] = sc;
        shift[c] = b[c] - mean * sc;
    }
}

// ---------------- split helpers ----------------
__device__ __forceinline__ void split4(float4 v, __nv_bfloat16* hi, __nv_bfloat16* lo,
                                       size_t off) {
    __nv_bfloat16 h0 = __float2bfloat16(v.x), h1 = __float2bfloat16(v.y);
    __nv_bfloat16 h2 = __float2bfloat16(v.z), h3 = __float2bfloat16(v.w);
    *(__nv_bfloat162*)(hi + off)     = __nv_bfloat162(h0, h1);
    *(__nv_bfloat162*)(hi + off + 2) = __nv_bfloat162(h2, h3);
    *(__nv_bfloat162*)(lo + off) = __nv_bfloat162(
        __float2bfloat16(v.x - __bfloat162float(h0)),
        __float2bfloat16(v.y - __bfloat162float(h1)));
    *(__nv_bfloat162*)(lo + off + 2) = __nv_bfloat162(
        __float2bfloat16(v.z - __bfloat162float(h2)),
        __float2bfloat16(v.w - __bfloat162float(h3)));
}

__global__ void splitW_all(const float* __restrict__ Wq, const float* __restrict__ Wk,
                           const float* __restrict__ Wv, const float* __restrict__ Wo,
                           const float* __restrict__ W0, const float* __restrict__ W1,
                           __nv_bfloat16* __restrict__ hi, __nv_bfloat16* __restrict__ lo) {
    int i = blockIdx.x * blockDim.x + threadIdx.x;    // 0..131071
    const float* src; int local;
    if (i < 16384)       { src = Wq; local = i; }
    else if (i < 32768)  { src = Wk; local = i - 16384; }
    else if (i < 49152)  { src = Wv; local = i - 32768; }
    else if (i < 65536)  { src = Wo; local = i - 49152; }
    else if (i < 98304)  { src = W0; local = i - 65536; }
    else                 { src = W1; local = i - 98304; }
    split4(((const float4*)src)[local], hi, lo, (size_t)i * 4);
}

// ---------------- mma.sync / cp.async helpers ----------------
__device__ __forceinline__ uint32_t smem_u32(const void* p) {
    uint32_t a;
    asm("{ .reg .u64 t; cvta.to.shared.u64 t, %1; cvt.u32.u64 %0, t; }" : "=r"(a) : "l"(p));
    return a;
}
__device__ __forceinline__ void ldm_x4(uint32_t* r, uint32_t addr) {
    asm volatile("ldmatrix.sync.aligned.m8n8.x4.shared.b16 {%0,%1,%2,%3}, [%4];"
                 : "=r"(r[0]), "=r"(r[1]), "=r"(r[2]), "=r"(r[3]) : "r"(addr));
}
__device__ __forceinline__ void ldm_x2(uint32_t* r, uint32_t addr) {
    asm volatile("ldmatrix.sync.aligned.m8n8.x2.shared.b16 {%0,%1}, [%2];"
                 : "=r"(r[0]), "=r"(r[1]) : "r"(addr));
}
__device__ __forceinline__ void mma_bf16(float* c, const uint32_t* a, const uint32_t* b) {
    asm volatile(
        "mma.sync.aligned.m16n8k16.row.col.f32.bf16.bf16.f32 "
        "{%0,%1,%2,%3}, {%4,%5,%6,%7}, {%8,%9}, {%0,%1,%2,%3};"
        : "+f"(c[0]), "+f"(c[1]), "+f"(c[2]), "+f"(c[3])
        : "r"(a[0]), "r"(a[1]), "r"(a[2]), "r"(a[3]), "r"(b[0]), "r"(b[1]));
}
__device__ __forceinline__ void cp16(uint32_t dst, const void* src) {
    asm volatile("cp.async.cg.shared.global [%0], [%1], 16;" :: "r"(dst), "l"(src));
}
__device__ __forceinline__ void cp_commit() {
    asm volatile("cp.async.commit_group;" ::: "memory");
}
template<int N> __device__ __forceinline__ void cp_wait() {
    asm volatile("cp.async.wait_group %0;" :: "n"(N) : "memory");
}

// ---------------- fused split-bf16 GEMM, 128x128 tile, 1-barrier pipeline ---
// Cout[M,N] = split(op(A_f32))[M,K] @ (Bh+Bl)[N,K]^T  (+ bias, + residual)
// 8 warps 2M x 4N (warp 64x32), K-chunk 32.
// A: 2 stages (LDG->regs->affine/split->STS). B: 3 stages (cp.async).
// STATS: epilogue also emits per-CTA column sum/sumsq partials into
// psum_g/psq_g at part index blockIdx.y (deterministic tree reduction).
// SMEM: [A: 2 x 20480][B: 3 x 20480][scales 4096] = 106496 B, 2 CTAs/SM.
#define ASTAGE 20480
#define BSTAGE 20480
#define AHALF  10240
#define B_BASE (2*ASTAGE)
#define SC_OFF (2*ASTAGE + 3*BSTAGE)
#define MMA_SMEM (SC_OFF + 4096)

template<int MODE, bool AFFINE, bool RELU, bool BIAS, bool RES, bool STATS>
__global__ void __launch_bounds__(256, 2)
mma_gemm(const float* __restrict__ A,
         const float* __restrict__ scale, const float* __restrict__ shift,
         const __nv_bfloat16* __restrict__ b_hi, const __nv_bfloat16* __restrict__ b_lo,
         float* __restrict__ Cout,
         __nv_bfloat16* __restrict__ q_hi, __nv_bfloat16* __restrict__ q_lo,
         __nv_bfloat16* __restrict__ k_hi, __nv_bfloat16* __restrict__ k_lo,
         const float* __restrict__ bias, const float* __restrict__ res,
         float* __restrict__ psum_g, float* __restrict__ psq_g,
         int M_, int N_, int K_) {
    extern __shared__ __align__(16) char sb[];
    const uint32_t sb32 = smem_u32(sb);
    float* sSc = (float*)(sb + SC_OFF);
    float* sSh = (float*)(sb + SC_OFF + 2048);

    const int t = threadIdx.x;
    const int lane = t & 31, warp = t >> 5;
    const int wm = warp & 1, wn = warp >> 1;
    const int row0 = blockIdx.y * 128, col0 = blockIdx.x * 128;

    if (AFFINE) {
        for (int i = t; i < K_; i += 256) { sSc[i] = scale[i]; sSh[i] = shift[i]; }
    }

    float acc[4][4][4];
    #pragma unroll
    for (int mi = 0; mi < 4; mi++)
        #pragma unroll
        for (int ni = 0; ni < 4; ni++)
            #pragma unroll
            for (int x = 0; x < 4; x++) acc[mi][ni][x] = 0.f;

    float4 aR[4];
    auto ldgA = [&](int k0) {
        #pragma unroll
        for (int i = 0; i < 4; i++) {
            int idx = t + i * 256;
            int r = idx >> 3, q = idx & 7;
            aR[i] = *(const float4*)&A[(size_t)(row0 + r) * K_ + k0 + q * 4];
        }
    };
    auto stsA = [&](int s, int k0) {
        char* base = sb + s * ASTAGE;
        #pragma unroll
        for (int i = 0; i < 4; i++) {
            int idx = t + i * 256;
            int r = idx >> 3, q = idx & 7;
            float4 v = aR[i];
            if (AFFINE) {
                int kc = k0 + q * 4;
                v.x = v.x * sSc[kc+0] + sSh[kc+0];
                v.y = v.y * sSc[kc+1] + sSh[kc+1];
                v.z = v.z * sSc[kc+2] + sSh[kc+2];
                v.w = v.w * sSc[kc+3] + sSh[kc+3];
                if (RELU) {
                    v.x = fmaxf(v.x, 0.f); v.y = fmaxf(v.y, 0.f);
                    v.z = fmaxf(v.z, 0.f); v.w = fmaxf(v.w, 0.f);
                }
            }
            __nv_bfloat16 h0 = __float2bfloat16(v.x), h1 = __float2bfloat16(v.y);
            __nv_bfloat16 h2 = __float2bfloat16(v.z), h3 = __float2bfloat16(v.w);
            __nv_bfloat162 hA(h0, h1), hB(h2, h3);
            __nv_bfloat162 lA(__float2bfloat16(v.x - __bfloat162float(h0)),
                              __float2bfloat16(v.y - __bfloat162float(h1)));
            __nv_bfloat162 lB(__float2bfloat16(v.z - __bfloat162float(h2)),
                              __float2bfloat16(v.w - __bfloat162float(h3)));
            int off = r * 80 + q * 8;
            *(__nv_bfloat162*)(base + off)             = hA;
            *(__nv_bfloat162*)(base + off + 4)         = hB;
            *(__nv_bfloat162*)(base + AHALF + off)     = lA;
            *(__nv_bfloat162*)(base + AHALF + off + 4) = lB;
        }
    };
    auto cpB = [&](int s, int k0) {
        uint32_t base = sb32 + B_BASE + s * BSTAGE;
        #pragma unroll
        for (int i = 0; i < 2; i++) {
            int idx = t + i * 256;
            int r = idx >> 2, qq = idx & 3;
            uint32_t off = (uint32_t)(r * 80 + qq * 16);
            size_t gb = (size_t)(col0 + r) * K_ + k0 + qq * 8;
            cp16(base + off,         b_hi + gb);
            cp16(base + AHALF + off, b_lo + gb);
        }
        cp_commit();
    };
    auto compute = [&](int sa, int sbuf) {
        uint32_t abase = sb32 + sa * ASTAGE;
        uint32_t bbase = sb32 + B_BASE + sbuf * BSTAGE;
        #pragma unroll
        for (int kk = 0; kk < 2; kk++) {
            uint32_t bh[4][2], bl[4][2];
            #pragma unroll
            for (int ni = 0; ni < 4; ni++) {
                int r = wn * 32 + ni * 8 + (lane & 7);
                int cbyte = (kk * 16 + ((lane >> 3) & 1) * 8) * 2;
                uint32_t addr = bbase + r * 80 + cbyte;
                ldm_x2(bh[ni], addr);
                ldm_x2(bl[ni], addr + AHALF);
            }
            #pragma unroll
            for (int mi = 0; mi < 4; mi++) {
                uint32_t ah[4], al[4];
                int r = wm * 64 + mi * 16 + (lane & 15);
                int cbyte = (kk * 16 + ((lane >> 4) << 3)) * 2;
                uint32_t addr = abase + r * 80 + cbyte;
                ldm_x4(ah, addr);
                ldm_x4(al, addr + AHALF);
                #pragma unroll
                for (int ni = 0; ni < 4; ni++) {
                    mma_bf16(acc[mi][ni], ah, bh[ni]);
                    mma_bf16(acc[mi][ni], ah, bl[ni]);
                    mma_bf16(acc[mi][ni], al, bh[ni]);
                }
            }
        }
    };

    const int nchunk = K_ >> 5;
    ldgA(0);
    cpB(0, 0);
    if (nchunk > 1) cpB(1, 32);
    __syncthreads();                  // scales visible for stsA
    stsA(0, 0);
    if (nchunk > 1) ldgA(32);

    for (int ch = 0; ch < nchunk; ch++) {
        if (ch + 1 < nchunk) cp_wait<1>(); else cp_wait<0>();
        __syncthreads();
        if (ch + 1 < nchunk) stsA((ch + 1) & 1, (ch + 1) * 32);
        compute(ch & 1, ch % 3);
        if (ch + 2 < nchunk) {
            ldgA((ch + 2) * 32);
            cpB((ch + 2) % 3, (ch + 2) * 32);
        }
    }

    // ---- epilogue ----
    const int tr = lane >> 2, tc = (lane & 3) * 2;
    float csum[4][2], csq[4][2];
    if (STATS) {
        #pragma unroll
        for (int ni = 0; ni < 4; ni++) {
            csum[ni][0] = csum[ni][1] = 0.f;
            csq[ni][0]  = csq[ni][1]  = 0.f;
        }
    }
    #pragma unroll
    for (int mi = 0; mi < 4; mi++) {
        #pragma unroll
        for (int ni = 0; ni < 4; ni++) {
            int rr = row0 + wm * 64 + mi * 16 + tr;
            int cc = col0 + wn * 32 + ni * 8 + tc;
            float v0 = acc[mi][ni][0], v1 = acc[mi][ni][1];
            float v2 = acc[mi][ni][2], v3 = acc[mi][ni][3];
            if (MODE == 2) {
                int dest = col0 >> 8;
                int ccl = cc - dest * 256;
                if (dest < 2) {
                    __nv_bfloat16* dh = (dest == 0) ? q_hi : k_hi;
                    __nv_bfloat16* dl = (dest == 0) ? q_lo : k_lo;
                    __nv_bfloat16 h0 = __float2bfloat16(v0), h1 = __float2bfloat16(v1);
                    __nv_bfloat16 h2 = __float2bfloat16(v2), h3 = __float2bfloat16(v3);
                    *(__nv_bfloat162*)(dh + (size_t)rr * 256 + ccl)     = __nv_bfloat162(h0, h1);
                    *(__nv_bfloat162*)(dh + (size_t)(rr+8) * 256 + ccl) = __nv_bfloat162(h2, h3);
                    *(__nv_bfloat162*)(dl + (size_t)rr * 256 + ccl) = __nv_bfloat162(
                        __float2bfloat16(v0 - __bfloat162float(h0)),
                        __float2bfloat16(v1 - __bfloat162float(h1)));
                    *(__nv_bfloat162*)(dl + (size_t)(rr+8) * 256 + ccl) = __nv_bfloat162(
                        __float2bfloat16(v2 - __bfloat162float(h2)),
                        __float2bfloat16(v3 - __bfloat162float(h3)));
                } else {
                    *(float2*)&Cout[(size_t)rr * 256 + ccl]     = make_float2(v0, v1);
                    *(float2*)&Cout[(size_t)(rr+8) * 256 + ccl] = make_float2(v2, v3);
                }
            } else {
                if (BIAS) { v0 += bias[cc]; v1 += bias[cc+1]; v2 += bias[cc]; v3 += bias[cc+1]; }
                if (RES) {
                    const float2 r0v = *(const float2*)&res[(size_t)rr * N_ + cc];
                    const float2 r1v = *(const float2*)&res[(size_t)(rr+8) * N_ + cc];
                    v0 += r0v.x; v1 += r0v.y; v2 += r1v.x; v3 += r1v.y;
                }
                if (STATS) {
                    csum[ni][0] += v0 + v2;       csum[ni][1] += v1 + v3;
                    csq[ni][0]  += v0*v0 + v2*v2; csq[ni][1]  += v1*v1 + v3*v3;
                }
                *(float2*)&Cout[(size_t)rr * N_ + cc]     = make_float2(v0, v1);
                *(float2*)&Cout[(size_t)(rr+8) * N_ + cc] = make_float2(v2, v3);
            }
        }
    }
    if (STATS) {
        // reduce over tr (lane bits 2..4): lanes 0..3 end with warp column totals
        #pragma unroll
        for (int off = 4; off <= 16; off <<= 1) {
            #pragma unroll
            for (int ni = 0; ni < 4; ni++) {
                csum[ni][0] += __shfl_xor_sync(0xffffffffu, csum[ni][0], off);
                csum[ni][1] += __shfl_xor_sync(0xffffffffu, csum[ni][1], off);
                csq[ni][0]  += __shfl_xor_sync(0xffffffffu, csq[ni][0], off);
                csq[ni][1]  += __shfl_xor_sync(0xffffffffu, csq[ni][1], off);
            }
        }
        __syncthreads();                  // smem stages no longer needed
        float* red = (float*)sb;          // [0..255]=sum, [256..511]=sq
        if (lane < 4) {
            #pragma unroll
            for (int ni = 0; ni < 4; ni++) {
                int cl = ni * 8 + (lane & 3) * 2;
                red[warp * 32 + cl]           = csum[ni][0];
                red[warp * 32 + cl + 1]       = csum[ni][1];
                red[256 + warp * 32 + cl]     = csq[ni][0];
                red[256 + warp * 32 + cl + 1] = csq[ni][1];
            }
        }
        __syncthreads();
        if (t < 128) {
            int wnn = t >> 5, cl = t & 31;
            float s = red[(2*wnn) * 32 + cl] + red[(2*wnn+1) * 32 + cl];
            float q = red[256 + (2*wnn) * 32 + cl] + red[256 + (2*wnn+1) * 32 + cl];
            size_t gi = (size_t)blockIdx.y * N_ + col0 + wnn * 32 + cl;
            psum_g[gi] = s;
            psq_g[gi]  = q;
        }
    }
}

// ---------------- energy via mma.sync (fp32 output) ----------------
#define ETILE 10240
__global__ void __launch_bounds__(256, 2)
energy_mma(const __nv_bfloat16* __restrict__ qhi, const __nv_bfloat16* __restrict__ qlo,
           const __nv_bfloat16* __restrict__ khi, const __nv_bfloat16* __restrict__ klo,
           float* __restrict__ E) {
    __shared__ __align__(16) char sb[4 * ETILE];
    const uint32_t sb32 = smem_u32(sb);
    const int nh = blockIdx.x;
    const int n = nh >> 3, h = nh & 7;
    const int t = threadIdx.x;
    const int lane = t & 31, warp = t >> 5;
    const int wm = warp & 1, wn = warp >> 1;

    const __nv_bfloat16* qh = qhi + ((size_t)(n * S) * H + h) * D;
    const __nv_bfloat16* ql = qlo + ((size_t)(n * S) * H + h) * D;
    const __nv_bfloat16* kh = khi + ((size_t)(n * S) * H + h) * D;
    const __nv_bfloat16* kl = klo + ((size_t)(n * S) * H + h) * D;

    #pragma unroll
    for (int i = 0; i < 2; i++) {
        int idx = t + i * 256;
        int r = idx >> 2, qq = idx & 3;
        size_t g = (size_t)r * (H * D) + qq * 8;
        uint32_t off = (uint32_t)(r * 80 + qq * 16);
        cp16(sb32 + off,             qh + g);
        cp16(sb32 + ETILE   + off,   ql + g);
        cp16(sb32 + 2*ETILE + off,   kh + g);
        cp16(sb32 + 3*ETILE + off,   kl + g);
    }
    cp_commit();
    cp_wait<0>();
    __syncthreads();

    float acc[4][4][4];
    #pragma unroll
    for (int mi = 0; mi < 4; mi++)
        #pragma unroll
        for (int ni = 0; ni < 4; ni++)
            #pragma unroll
            for (int x = 0; x < 4; x++) acc[mi][ni][x] = 0.f;

    #pragma unroll
    for (int kk = 0; kk < 2; kk++) {
        uint32_t bh[4][2], bl[4][2];
        #pragma unroll
        for (int ni = 0; ni < 4; ni++) {
            int r = wn * 32 + ni * 8 + (lane & 7);
            int cbyte = (kk * 16 + ((lane >> 3) & 1) * 8) * 2;
            uint32_t addr = sb32 + 2*ETILE + r * 80 + cbyte;
            ldm_x2(bh[ni], addr);
            ldm_x2(bl[ni], addr + ETILE);
        }
        #pragma unroll
        for (int mi = 0; mi < 4; mi++) {
            uint32_t ah[4], al[4];
            int r = wm * 64 + mi * 16 + (lane & 15);
            int cbyte = (kk * 16 + ((lane >> 4) << 3)) * 2;
            uint32_t addr = sb32 + r * 80 + cbyte;
            ldm_x4(ah, addr);
            ldm_x4(al, addr + ETILE);
            #pragma unroll
            for (int ni = 0; ni < 4; ni++) {
                mma_bf16(acc[mi][ni], ah, bh[ni]);
                mma_bf16(acc[mi][ni], ah, bl[ni]);
                mma_bf16(acc[mi][ni], al, bh[ni]);
            }
        }
    }

    float* eb = E + (size_t)nh * SSQ;
    const int tr = lane >> 2, tc = (lane & 3) * 2;
    #pragma unroll
    for (int mi = 0; mi < 4; mi++)
        #pragma unroll
        for (int ni = 0; ni < 4; ni++) {
            int rr = wm * 64 + mi * 16 + tr;
            int cc = wn * 32 + ni * 8 + tc;
            *(float2*)&eb[(size_t)rr * S + cc]     = make_float2(acc[mi][ni][0], acc[mi][ni][1]);
            *(float2*)&eb[(size_t)(rr+8) * S + cc] = make_float2(acc[mi][ni][2], acc[mi][ni][3]);
        }
}

// ---------------- fused BN(affine) + softmax + AV, fp32 output --------------
#define SAV_SMEM (128*129*4 + 128*36*4)

typedef unsigned long long u64;
__device__ __forceinline__ u64 pack2(float x) {
    u64 r; unsigned u = __float_as_uint(x);
    asm("mov.b64 %0, {%1, %1};" : "=l"(r) : "r"(u));
    return r;
}
__device__ __forceinline__ void ffma2(u64& d, u64 a, u64 b) {
    asm("fma.rn.f32x2 %0, %1, %2, %0;" : "+l"(d) : "l"(a), "l"(b));
}
__device__ __forceinline__ float lo32(u64 v) { return __uint_as_float((unsigned)v); }
__device__ __forceinline__ float hi32(u64 v) { return __uint_as_float((unsigned)(v >> 32)); }

__global__ void __launch_bounds__(256, 2)
softmax_av(const float* __restrict__ E,
           const float* __restrict__ scpe, const float* __restrict__ shpe,
           const float* __restrict__ V, float* __restrict__ O) {
    extern __shared__ __align__(16) float smf[];
    float* attn = smf;
    float* vs   = smf + 128 * 129;
    const int nh = blockIdx.x;
    const int n = nh >> 3, h = nh & 7;
    const int t = threadIdx.x;
    const int lane = t & 31, warp = t >> 5;

    const float* vb = V + ((size_t)(n * S) * H + h) * D;
    #pragma unroll
    for (int i = 0; i < 4; i++) {
        int idx = t + i * 256;
        int l = idx >> 3, qq = idx & 7;
        *(float4*)&vs[l * 36 + qq * 4] = *(const float4*)&vb[(size_t)l * (H * D) + qq * 4];
    }

    const float* eb = E + (size_t)nh * SSQ;
    for (int rr = 0; rr < 16; rr++) {
        int row = warp * 16 + rr;
        const float* e = eb + (size_t)row * S;
        const float* sc = scpe + row * S;
        const float* sh = shpe + row * S;
        float v[4];
        float mx = -INFINITY;
        #pragma unroll
        for (int i = 0; i < 4; i++) {
            int ki = i * 32 + lane;
            v[i] = (e[ki] * sc[ki] + sh[ki]) * 0.0625f;
            mx = fmaxf(mx, v[i]);
        }
        #pragma unroll
        for (int off = 16; off > 0; off >>= 1)
            mx = fmaxf(mx, __shfl_xor_sync(0xffffffffu, mx, off));
        float sum = 0.f;
        #pragma unroll
        for (int i = 0; i < 4; i++) { v[i] = __expf(v[i] - mx); sum += v[i]; }
        #pragma unroll
        for (int off = 16; off > 0; off >>= 1)
            sum += __shfl_xor_sync(0xffffffffu, sum, off);
        float inv = 1.f / sum;
        #pragma unroll
        for (int i = 0; i < 4; i++)
            attn[row * 129 + i * 32 + lane] = v[i] * inv;
    }
    __syncthreads();

    const int ty = t >> 3, tx = t & 7;
    u64 acc[4][2];
    #pragma unroll
    for (int i = 0; i < 4; i++) { acc[i][0] = 0ull; acc[i][1] = 0ull; }
    for (int l = 0; l < 128; l++) {
        u64 b0 = *(const u64*)&vs[l * 36 + tx * 4];
        u64 b1 = *(const u64*)&vs[l * 36 + tx * 4 + 2];
        #pragma unroll
        for (int i = 0; i < 4; i++) {
            u64 ad = pack2(attn[(ty * 4 + i) * 129 + l]);
            ffma2(acc[i][0], ad, b0);
            ffma2(acc[i][1], ad, b1);
        }
    }
    #pragma unroll
    for (int i = 0; i < 4; i++) {
        int qrow = ty * 4 + i;
        size_t base = ((size_t)(n * S + qrow) * H + h) * D + tx * 4;
        *(float4*)&O[base] = make_float4(lo32(acc[i][0]), hi32(acc[i][0]),
                                         lo32(acc[i][1]), hi32(acc[i][1]));
    }
}

// ---------------------------------------------------------------------------
extern "C" void kernel_launch(void* const* d_in, const int* in_sizes, int n_in,
                              void* d_out, int out_size) {
    const float* x    = (const float*)d_in[0];
    const float* g_n  = (const float*)d_in[1];
    const float* b_n  = (const float*)d_in[2];
    const float* Wq   = (const float*)d_in[3];
    const float* Wk   = (const float*)d_in[4];
    const float* Wv   = (const float*)d_in[5];
    const float* Wo   = (const float*)d_in[6];
    const float* bo   = (const float*)d_in[7];
    const float* g_pe = (const float*)d_in[8];
    const float* b_pe = (const float*)d_in[9];
    const float* g0   = (const float*)d_in[10];
    const float* b0   = (const float*)d_in[11];
    const float* W0   = (const float*)d_in[12];
    const float* g1   = (const float*)d_in[13];
    const float* b1   = (const float*)d_in[14];
    const float* W1   = (const float*)d_in[15];
    float* out = (float*)d_out;

    float *v, *o, *e, *x1, *t2, *psum, *psq, *sc, *sh, *scpe, *shpe;
    __nv_bfloat16 *whi, *wlo, *qhi, *qlo, *khi, *klo;
    cudaGetSymbolAddress((void**)&v,    g_v);
    cudaGetSymbolAddress((void**)&o,    g_o);
    cudaGetSymbolAddress((void**)&e,    g_e);
    cudaGetSymbolAddress((void**)&x1,   g_x1);
    cudaGetSymbolAddress((void**)&t2,   g_t2);
    cudaGetSymbolAddress((void**)&psum, g_psum);
    cudaGetSymbolAddress((void**)&psq,  g_psq);
    cudaGetSymbolAddress((void**)&sc,   g_scale);
    cudaGetSymbolAddress((void**)&sh,   g_shift);
    cudaGetSymbolAddress((void**)&scpe, g_scale_pe);
    cudaGetSymbolAddress((void**)&shpe, g_shift_pe);
    cudaGetSymbolAddress((void**)&whi,  g_whi);
    cudaGetSymbolAddress((void**)&wlo,  g_wlo);
    cudaGetSymbolAddress((void**)&qhi,  g_qhi);
    cudaGetSymbolAddress((void**)&qlo,  g_qlo);
    cudaGetSymbolAddress((void**)&khi,  g_khi);
    cudaGetSymbolAddress((void**)&klo,  g_klo);

    cudaFuncSetAttribute(mma_gemm<2,true ,false,false,false,false>, cudaFuncAttributeMaxDynamicSharedMemorySize, MMA_SMEM);
    cudaFuncSetAttribute(mma_gemm<0,false,false,true ,true ,true >, cudaFuncAttributeMaxDynamicSharedMemorySize, MMA_SMEM);
    cudaFuncSetAttribute(mma_gemm<0,true ,true ,false,false,true >, cudaFuncAttributeMaxDynamicSharedMemorySize, MMA_SMEM);
    cudaFuncSetAttribute(mma_gemm<0,true ,true ,false,true ,false>, cudaFuncAttributeMaxDynamicSharedMemorySize, MMA_SMEM);
    cudaFuncSetAttribute(softmax_av, cudaFuncAttributeMaxDynamicSharedMemorySize, SAV_SMEM);

    // split all weights (one launch, no deps)
    splitW_all<<<512, 256>>>(Wq, Wk, Wv, Wo, W0, W1, whi, wlo);

    // BN over C on x
    bn_partial<<<dim3(1, 256), 256>>>(x, C, 128, psum, psq);
    bn_finalize_warp<<<C / 8, 256>>>(psum, psq, C, 256, 1.f / MROWS, g_n, b_n, sc, sh);

    // fused QKV GEMM (128-col tiles: tiles 0-1 -> q, 2-3 -> k, 4-5 -> v)
    dim3 gq(768 / 128, MROWS / 128);
    mma_gemm<2,true,false,false,false,false><<<gq, 256, MMA_SMEM>>>(x, sc, sh, whi, wlo,
        v, qhi, qlo, khi, klo, nullptr, nullptr, nullptr, nullptr, MROWS, 768, C);

    // energy (fp32 out)
    energy_mma<<<NHB, 256>>>(qhi, qlo, khi, klo, e);

    // BN over S*S on energy (16 partials)
    bn_partial<<<dim3(SSQ / 256, 16), 256>>>(e, SSQ, 128, psum, psq);
    bn_finalize<<<SSQ / 256, 256>>>(psum, psq, SSQ, 16, 1.f / NHB, g_pe, b_pe, scpe, shpe);

    // fused BN + softmax + AV -> fp32 o
    softmax_av<<<NHB, 256, SAV_SMEM>>>(e, scpe, shpe, v, o);

    // x1 = o @ Wo^T + bo + x, with fused BN0 column partials
    dim3 go(C / 128, MROWS / 128);
    mma_gemm<0,false,false,true,true,true><<<go, 256, MMA_SMEM>>>(o, nullptr, nullptr,
        whi + WOFF_O, wlo + WOFF_O, x1, nullptr, nullptr, nullptr, nullptr, bo, x,
        psum, psq, MROWS, C, C);

    // BN0 finalize (partials already produced by Wo GEMM)
    bn_finalize_warp<<<C / 8, 256>>>(psum, psq, C, 256, 1.f / MROWS, g0, b0, sc, sh);

    // FFN0 GEMM (affine+relu fused on A), with fused BN1 column partials
    dim3 gf0(C2 / 128, MROWS / 128);
    mma_gemm<0,true,true,false,false,true><<<gf0, 256, MMA_SMEM>>>(x1, sc, sh,
        whi + WOFF_0, wlo + WOFF_0, t2, nullptr, nullptr, nullptr, nullptr, nullptr, nullptr,
        psum, psq, MROWS, C2, C);

    // BN1 finalize (partials already produced by FFN0 GEMM)
    bn_finalize_warp<<<C2 / 8, 256>>>(psum, psq, C2, 256, 1.f / MROWS, g1, b1, sc, sh);

    // FFN1 GEMM (affine+relu fused on A) + x1 residual -> out
    mma_gemm<0,true,true,false,true,false><<<go, 256, MMA_SMEM>>>(t2, sc, sh,
        whi + WOFF_1, wlo + WOFF_1, out, nullptr, nullptr, nullptr, nullptr, nullptr, x1,
        nullptr, nullptr, MROWS, C, C2);
}

// round 17
// speedup vs baseline: 1.1382x; 1.0283x over previous
#include <cuda_runtime.h>
#include <cuda_bf16.h>
#include <math.h>
#include <stdint.h>

// Problem constants
#define MB  256
#define S   128
#define C   256
#define H   8
#define D   32
#define MROWS (MB*S)           // 32768
#define C2  (2*C)              // 512
#define NHB (MB*H)             // 2048
#define SSQ (S*S)              // 16384

// weight offsets inside the packed split-weight buffer
#define WOFF_O   196608         // 768*256
#define WOFF_0   262144         // + 256*256
#define WOFF_1   393216         // + 512*256   (total 524288)

// ---------------- scratch (device globals) ----------------
__device__ float g_v [MROWS*C];
__device__ float g_o [MROWS*C];
__device__ float g_e [NHB*SSQ];
__device__ float g_x1[MROWS*C];
__device__ float g_t2[MROWS*C2];
__device__ float g_psum[262144];
__device__ float g_psq [262144];
__device__ float g_scale[C2];
__device__ float g_shift[C2];
__device__ float g_scale_pe[SSQ];
__device__ float g_shift_pe[SSQ];
__device__ __nv_bfloat16 g_whi[524288];
__device__ __nv_bfloat16 g_wlo[524288];
__device__ __nv_bfloat16 g_qhi[MROWS*C];
__device__ __nv_bfloat16 g_qlo[MROWS*C];
__device__ __nv_bfloat16 g_khi[MROWS*C];
__device__ __nv_bfloat16 g_klo[MROWS*C];

// ---------------- BN stats: deterministic 2-stage reduction ----------------
__global__ void bn_partial(const float* __restrict__ X, int Cdim, int rowsPerBlock,
                           float* __restrict__ psum, float* __restrict__ psq) {
    int c = blockIdx.x * blockDim.x + threadIdx.x;
    int r0 = blockIdx.y * rowsPerBlock;
    float s = 0.f, q = 0.f;
    const float* Xp = X + (size_t)r0 * Cdim + c;
    for (int i = 0; i < rowsPerBlock; i++) {
        float v = Xp[(size_t)i * Cdim];
        s += v; q += v * v;
    }
    psum[(size_t)blockIdx.y * Cdim + c] = s;
    psq [(size_t)blockIdx.y * Cdim + c] = q;
}

// per-thread finalize (energy BN: many channels, few parts)
__global__ void bn_finalize(const float* __restrict__ psum, const float* __restrict__ psq,
                            int Cdim, int nparts, float invM,
                            const float* __restrict__ g, const float* __restrict__ b,
                            float* __restrict__ scale, float* __restrict__ shift) {
    int c = blockIdx.x * blockDim.x + threadIdx.x;
    float s = 0.f, q = 0.f;
    for (int p = 0; p < nparts; p++) {
        s += psum[(size_t)p * Cdim + c];
        q += psq [(size_t)p * Cdim + c];
    }
    float mean = s * invM;
    float var  = q * invM - mean * mean;
    float sc   = g[c] * rsqrtf(var + 1e-5f);
    scale[c] = sc;
    shift[c] = b[c] - mean * sc;
}

// warp-per-channel finalize (few channels, many parts)
__global__ void bn_finalize_warp(const float* __restrict__ psum, const float* __restrict__ psq,
                                 int Cdim, int nparts, float invM,
                                 const float* __restrict__ g, const float* __restrict__ b,
                                 float* __restrict__ scale, float* __restrict__ shift) {
    int warp = threadIdx.x >> 5, lane = threadIdx.x & 31;
    int c = blockIdx.x * 8 + warp;
    float s = 0.f, q = 0.f;
    for (int p = lane; p < nparts; p += 32) {
        s += psum[(size_t)p * Cdim + c];
        q += psq [(size_t)p * Cdim + c];
    }
    #pragma unroll
    for (int off = 16; off > 0; off >>= 1) {
        s += __shfl_xor_sync(0xffffffffu, s, off);
        q += __shfl_xor_sync(0xffffffffu, q, off);
    }
    if (lane == 0) {
        float mean = s * invM;
        float var  = q * invM - mean * mean;
        float sc   = g[c] * rsqrtf(var + 1e-5f);
        scale[c] = sc;
        shift[c] = b[c] - mean * sc;
    }
}

// ---------------- split helpers ----------------
__device__ __forceinline__ void split4(float4 v, __nv_bfloat16* hi, __nv_bfloat16* lo,
                                       size_t off) {
    __nv_bfloat16 h0 = __float2bfloat16(v.x), h1 = __float2bfloat16(v.y);
    __nv_bfloat16 h2 = __float2bfloat16(v.z), h3 = __float2bfloat16(v.w);
    *(__nv_bfloat162*)(hi + off)     = __nv_bfloat162(h0, h1);
    *(__nv_bfloat162*)(hi + off + 2) = __nv_bfloat162(h2, h3);
    *(__nv_bfloat162*)(lo + off) = __nv_bfloat162(
        __float2bfloat16(v.x - __bfloat162float(h0)),
        __float2bfloat16(v.y - __bfloat162float(h1)));
    *(__nv_bfloat162*)(lo + off + 2) = __nv_bfloat162(
        __float2bfloat16(v.z - __bfloat162float(h2)),
        __float2bfloat16(v.w - __bfloat162float(h3)));
}

__global__ void splitW_all(const float* __restrict__ Wq, const float* __restrict__ Wk,
                           const float* __restrict__ Wv, const float* __restrict__ Wo,
                           const float* __restrict__ W0, const float* __restrict__ W1,
                           __nv_bfloat16* __restrict__ hi, __nv_bfloat16* __restrict__ lo) {
    int i = blockIdx.x * blockDim.x + threadIdx.x;    // 0..131071
    const float* src; int local;
    if (i < 16384)       { src = Wq; local = i; }
    else if (i < 32768)  { src = Wk; local = i - 16384; }
    else if (i < 49152)  { src = Wv; local = i - 32768; }
    else if (i < 65536)  { src = Wo; local = i - 49152; }
    else if (i < 98304)  { src = W0; local = i - 65536; }
    else                 { src = W1; local = i - 98304; }
    split4(((const float4*)src)[local], hi, lo, (size_t)i * 4);
}

// ---------------- mma.sync / cp.async helpers ----------------
__device__ __forceinline__ uint32_t smem_u32(const void* p) {
    uint32_t a;
    asm("{ .reg .u64 t; cvta.to.shared.u64 t, %1; cvt.u32.u64 %0, t; }" : "=r"(a) : "l"(p));
    return a;
}
__device__ __forceinline__ void ldm_x4(uint32_t* r, uint32_t addr) {
    asm volatile("ldmatrix.sync.aligned.m8n8.x4.shared.b16 {%0,%1,%2,%3}, [%4];"
                 : "=r"(r[0]), "=r"(r[1]), "=r"(r[2]), "=r"(r[3]) : "r"(addr));
}
__device__ __forceinline__ void ldm_x2(uint32_t* r, uint32_t addr) {
    asm volatile("ldmatrix.sync.aligned.m8n8.x2.shared.b16 {%0,%1}, [%2];"
                 : "=r"(r[0]), "=r"(r[1]) : "r"(addr));
}
__device__ __forceinline__ void mma_bf16(float* c, const uint32_t* a, const uint32_t* b) {
    asm volatile(
        "mma.sync.aligned.m16n8k16.row.col.f32.bf16.bf16.f32 "
        "{%0,%1,%2,%3}, {%4,%5,%6,%7}, {%8,%9}, {%0,%1,%2,%3};"
        : "+f"(c[0]), "+f"(c[1]), "+f"(c[2]), "+f"(c[3])
        : "r"(a[0]), "r"(a[1]), "r"(a[2]), "r"(a[3]), "r"(b[0]), "r"(b[1]));
}
__device__ __forceinline__ void cp16(uint32_t dst, const void* src) {
    asm volatile("cp.async.cg.shared.global [%0], [%1], 16;" :: "r"(dst), "l"(src));
}
__device__ __forceinline__ void cp_commit() {
    asm volatile("cp.async.commit_group;" ::: "memory");
}
template<int N> __device__ __forceinline__ void cp_wait() {
    asm volatile("cp.async.wait_group %0;" :: "n"(N) : "memory");
}

// ---------------- fused split-bf16 GEMM, 128x128 tile, 1-barrier pipeline ---
#define ASTAGE 20480
#define BSTAGE 20480
#define AHALF  10240
#define B_BASE (2*ASTAGE)
#define SC_OFF (2*ASTAGE + 3*BSTAGE)
#define MMA_SMEM (SC_OFF + 4096)

template<int MODE, bool AFFINE, bool RELU, bool BIAS, bool RES, bool STATS>
__global__ void __launch_bounds__(256, 2)
mma_gemm(const float* __restrict__ A,
         const float* __restrict__ scale, const float* __restrict__ shift,
         const __nv_bfloat16* __restrict__ b_hi, const __nv_bfloat16* __restrict__ b_lo,
         float* __restrict__ Cout,
         __nv_bfloat16* __restrict__ q_hi, __nv_bfloat16* __restrict__ q_lo,
         __nv_bfloat16* __restrict__ k_hi, __nv_bfloat16* __restrict__ k_lo,
         const float* __restrict__ bias, const float* __restrict__ res,
         float* __restrict__ psum_g, float* __restrict__ psq_g,
         int M_, int N_, int K_) {
    extern __shared__ __align__(16) char sb[];
    const uint32_t sb32 = smem_u32(sb);
    float* sSc = (float*)(sb + SC_OFF);
    float* sSh = (float*)(sb + SC_OFF + 2048);

    const int t = threadIdx.x;
    const int lane = t & 31, warp = t >> 5;
    const int wm = warp & 1, wn = warp >> 1;
    const int row0 = blockIdx.y * 128, col0 = blockIdx.x * 128;

    if (AFFINE) {
        for (int i = t; i < K_; i += 256) { sSc[i] = scale[i]; sSh[i] = shift[i]; }
    }

    float acc[4][4][4];
    #pragma unroll
    for (int mi = 0; mi < 4; mi++)
        #pragma unroll
        for (int ni = 0; ni < 4; ni++)
            #pragma unroll
            for (int x = 0; x < 4; x++) acc[mi][ni][x] = 0.f;

    float4 aR[4];
    auto ldgA = [&](int k0) {
        #pragma unroll
        for (int i = 0; i < 4; i++) {
            int idx = t + i * 256;
            int r = idx >> 3, q = idx & 7;
            aR[i] = *(const float4*)&A[(size_t)(row0 + r) * K_ + k0 + q * 4];
        }
    };
    auto stsA = [&](int s, int k0) {
        char* base = sb + s * ASTAGE;
        #pragma unroll
        for (int i = 0; i < 4; i++) {
            int idx = t + i * 256;
            int r = idx >> 3, q = idx & 7;
            float4 v = aR[i];
            if (AFFINE) {
                int kc = k0 + q * 4;
                v.x = v.x * sSc[kc+0] + sSh[kc+0];
                v.y = v.y * sSc[kc+1] + sSh[kc+1];
                v.z = v.z * sSc[kc+2] + sSh[kc+2];
                v.w = v.w * sSc[kc+3] + sSh[kc+3];
                if (RELU) {
                    v.x = fmaxf(v.x, 0.f); v.y = fmaxf(v.y, 0.f);
                    v.z = fmaxf(v.z, 0.f); v.w = fmaxf(v.w, 0.f);
                }
            }
            __nv_bfloat16 h0 = __float2bfloat16(v.x), h1 = __float2bfloat16(v.y);
            __nv_bfloat16 h2 = __float2bfloat16(v.z), h3 = __float2bfloat16(v.w);
            __nv_bfloat162 hA(h0, h1), hB(h2, h3);
            __nv_bfloat162 lA(__float2bfloat16(v.x - __bfloat162float(h0)),
                              __float2bfloat16(v.y - __bfloat162float(h1)));
            __nv_bfloat162 lB(__float2bfloat16(v.z - __bfloat162float(h2)),
                              __float2bfloat16(v.w - __bfloat162float(h3)));
            int off = r * 80 + q * 8;
            *(__nv_bfloat162*)(base + off)             = hA;
            *(__nv_bfloat162*)(base + off + 4)         = hB;
            *(__nv_bfloat162*)(base + AHALF + off)     = lA;
            *(__nv_bfloat162*)(base + AHALF + off + 4) = lB;
        }
    };
    auto cpB = [&](int s, int k0) {
        uint32_t base = sb32 + B_BASE + s * BSTAGE;
        #pragma unroll
        for (int i = 0; i < 2; i++) {
            int idx = t + i * 256;
            int r = idx >> 2, qq = idx & 3;
            uint32_t off = (uint32_t)(r * 80 + qq * 16);
            size_t gb = (size_t)(col0 + r) * K_ + k0 + qq * 8;
            cp16(base + off,         b_hi + gb);
            cp16(base + AHALF + off, b_lo + gb);
        }
        cp_commit();
    };
    auto compute = [&](int sa, int sbuf) {
        uint32_t abase = sb32 + sa * ASTAGE;
        uint32_t bbase = sb32 + B_BASE + sbuf * BSTAGE;
        #pragma unroll
        for (int kk = 0; kk < 2; kk++) {
            uint32_t bh[4][2], bl[4][2];
            #pragma unroll
            for (int ni = 0; ni < 4; ni++) {
                int r = wn * 32 + ni * 8 + (lane & 7);
                int cbyte = (kk * 16 + ((lane >> 3) & 1) * 8) * 2;
                uint32_t addr = bbase + r * 80 + cbyte;
                ldm_x2(bh[ni], addr);
                ldm_x2(bl[ni], addr + AHALF);
            }
            #pragma unroll
            for (int mi = 0; mi < 4; mi++) {
                uint32_t ah[4], al[4];
                int r = wm * 64 + mi * 16 + (lane & 15);
                int cbyte = (kk * 16 + ((lane >> 4) << 3)) * 2;
                uint32_t addr = abase + r * 80 + cbyte;
                ldm_x4(ah, addr);
                ldm_x4(al, addr + AHALF);
                #pragma unroll
                for (int ni = 0; ni < 4; ni++) {
                    mma_bf16(acc[mi][ni], ah, bh[ni]);
                    mma_bf16(acc[mi][ni], ah, bl[ni]);
                    mma_bf16(acc[mi][ni], al, bh[ni]);
                }
            }
        }
    };

    const int nchunk = K_ >> 5;
    ldgA(0);
    cpB(0, 0);
    if (nchunk > 1) cpB(1, 32);
    __syncthreads();
    stsA(0, 0);
    if (nchunk > 1) ldgA(32);

    for (int ch = 0; ch < nchunk; ch++) {
        if (ch + 1 < nchunk) cp_wait<1>(); else cp_wait<0>();
        __syncthreads();
        if (ch + 1 < nchunk) stsA((ch + 1) & 1, (ch + 1) * 32);
        compute(ch & 1, ch % 3);
        if (ch + 2 < nchunk) {
            ldgA((ch + 2) * 32);
            cpB((ch + 2) % 3, (ch + 2) * 32);
        }
    }

    // ---- epilogue ----
    const int tr = lane >> 2, tc = (lane & 3) * 2;
    float csum[4][2], csq[4][2];
    if (STATS) {
        #pragma unroll
        for (int ni = 0; ni < 4; ni++) {
            csum[ni][0] = csum[ni][1] = 0.f;
            csq[ni][0]  = csq[ni][1]  = 0.f;
        }
    }
    #pragma unroll
    for (int mi = 0; mi < 4; mi++) {
        #pragma unroll
        for (int ni = 0; ni < 4; ni++) {
            int rr = row0 + wm * 64 + mi * 16 + tr;
            int cc = col0 + wn * 32 + ni * 8 + tc;
            float v0 = acc[mi][ni][0], v1 = acc[mi][ni][1];
            float v2 = acc[mi][ni][2], v3 = acc[mi][ni][3];
            if (MODE == 2) {
                int dest = col0 >> 8;
                int ccl = cc - dest * 256;
                if (dest < 2) {
                    __nv_bfloat16* dh = (dest == 0) ? q_hi : k_hi;
                    __nv_bfloat16* dl = (dest == 0) ? q_lo : k_lo;
                    __nv_bfloat16 h0 = __float2bfloat16(v0), h1 = __float2bfloat16(v1);
                    __nv_bfloat16 h2 = __float2bfloat16(v2), h3 = __float2bfloat16(v3);
                    *(__nv_bfloat162*)(dh + (size_t)rr * 256 + ccl)     = __nv_bfloat162(h0, h1);
                    *(__nv_bfloat162*)(dh + (size_t)(rr+8) * 256 + ccl) = __nv_bfloat162(h2, h3);
                    *(__nv_bfloat162*)(dl + (size_t)rr * 256 + ccl) = __nv_bfloat162(
                        __float2bfloat16(v0 - __bfloat162float(h0)),
                        __float2bfloat16(v1 - __bfloat162float(h1)));
                    *(__nv_bfloat162*)(dl + (size_t)(rr+8) * 256 + ccl) = __nv_bfloat162(
                        __float2bfloat16(v2 - __bfloat162float(h2)),
                        __float2bfloat16(v3 - __bfloat162float(h3)));
                } else {
                    *(float2*)&Cout[(size_t)rr * 256 + ccl]     = make_float2(v0, v1);
                    *(float2*)&Cout[(size_t)(rr+8) * 256 + ccl] = make_float2(v2, v3);
                }
            } else {
                if (BIAS) { v0 += bias[cc]; v1 += bias[cc+1]; v2 += bias[cc]; v3 += bias[cc+1]; }
                if (RES) {
                    const float2 r0v = *(const float2*)&res[(size_t)rr * N_ + cc];
                    const float2 r1v = *(const float2*)&res[(size_t)(rr+8) * N_ + cc];
                    v0 += r0v.x; v1 += r0v.y; v2 += r1v.x; v3 += r1v.y;
                }
                if (STATS) {
                    csum[ni][0] += v0 + v2;       csum[ni][1] += v1 + v3;
                    csq[ni][0]  += v0*v0 + v2*v2; csq[ni][1]  += v1*v1 + v3*v3;
                }
                *(float2*)&Cout[(size_t)rr * N_ + cc]     = make_float2(v0, v1);
                *(float2*)&Cout[(size_t)(rr+8) * N_ + cc] = make_float2(v2, v3);
            }
        }
    }
    if (STATS) {
        #pragma unroll
        for (int off = 4; off <= 16; off <<= 1) {
            #pragma unroll
            for (int ni = 0; ni < 4; ni++) {
                csum[ni][0] += __shfl_xor_sync(0xffffffffu, csum[ni][0], off);
                csum[ni][1] += __shfl_xor_sync(0xffffffffu, csum[ni][1], off);
                csq[ni][0]  += __shfl_xor_sync(0xffffffffu, csq[ni][0], off);
                csq[ni][1]  += __shfl_xor_sync(0xffffffffu, csq[ni][1], off);
            }
        }
        __syncthreads();
        float* red = (float*)sb;
        if (lane < 4) {
            #pragma unroll
            for (int ni = 0; ni < 4; ni++) {
                int cl = ni * 8 + (lane & 3) * 2;
                red[warp * 32 + cl]           = csum[ni][0];
                red[warp * 32 + cl + 1]       = csum[ni][1];
                red[256 + warp * 32 + cl]     = csq[ni][0];
                red[256 + warp * 32 + cl + 1] = csq[ni][1];
            }
        }
        __syncthreads();
        if (t < 128) {
            int wnn = t >> 5, cl = t & 31;
            float s = red[(2*wnn) * 32 + cl] + red[(2*wnn+1) * 32 + cl];
            float q = red[256 + (2*wnn) * 32 + cl] + red[256 + (2*wnn+1) * 32 + cl];
            size_t gi = (size_t)blockIdx.y * N_ + col0 + wnn * 32 + cl;
            psum_g[gi] = s;
            psq_g[gi]  = q;
        }
    }
}

// ---------------- energy via mma.sync (fp32 output) ----------------
#define ETILE 10240
__global__ void __launch_bounds__(256, 2)
energy_mma(const __nv_bfloat16* __restrict__ qhi, const __nv_bfloat16* __restrict__ qlo,
           const __nv_bfloat16* __restrict__ khi, const __nv_bfloat16* __restrict__ klo,
           float* __restrict__ E) {
    __shared__ __align__(16) char sb[4 * ETILE];
    const uint32_t sb32 = smem_u32(sb);
    const int nh = blockIdx.x;
    const int n = nh >> 3, h = nh & 7;
    const int t = threadIdx.x;
    const int lane = t & 31, warp = t >> 5;
    const int wm = warp & 1, wn = warp >> 1;

    const __nv_bfloat16* qh = qhi + ((size_t)(n * S) * H + h) * D;
    const __nv_bfloat16* ql = qlo + ((size_t)(n * S) * H + h) * D;
    const __nv_bfloat16* kh = khi + ((size_t)(n * S) * H + h) * D;
    const __nv_bfloat16* kl = klo + ((size_t)(n * S) * H + h) * D;

    #pragma unroll
    for (int i = 0; i < 2; i++) {
        int idx = t + i * 256;
        int r = idx >> 2, qq = idx & 3;
        size_t g = (size_t)r * (H * D) + qq * 8;
        uint32_t off = (uint32_t)(r * 80 + qq * 16);
        cp16(sb32 + off,             qh + g);
        cp16(sb32 + ETILE   + off,   ql + g);
        cp16(sb32 + 2*ETILE + off,   kh + g);
        cp16(sb32 + 3*ETILE + off,   kl + g);
    }
    cp_commit();
    cp_wait<0>();
    __syncthreads();

    float acc[4][4][4];
    #pragma unroll
    for (int mi = 0; mi < 4; mi++)
        #pragma unroll
        for (int ni = 0; ni < 4; ni++)
            #pragma unroll
            for (int x = 0; x < 4; x++) acc[mi][ni][x] = 0.f;

    #pragma unroll
    for (int kk = 0; kk < 2; kk++) {
        uint32_t bh[4][2], bl[4][2];
        #pragma unroll
        for (int ni = 0; ni < 4; ni++) {
            int r = wn * 32 + ni * 8 + (lane & 7);
            int cbyte = (kk * 16 + ((lane >> 3) & 1) * 8) * 2;
            uint32_t addr = sb32 + 2*ETILE + r * 80 + cbyte;
            ldm_x2(bh[ni], addr);
            ldm_x2(bl[ni], addr + ETILE);
        }
        #pragma unroll
        for (int mi = 0; mi < 4; mi++) {
            uint32_t ah[4], al[4];
            int r = wm * 64 + mi * 16 + (lane & 15);
            int cbyte = (kk * 16 + ((lane >> 4) << 3)) * 2;
            uint32_t addr = sb32 + r * 80 + cbyte;
            ldm_x4(ah, addr);
            ldm_x4(al, addr + ETILE);
            #pragma unroll
            for (int ni = 0; ni < 4; ni++) {
                mma_bf16(acc[mi][ni], ah, bh[ni]);
                mma_bf16(acc[mi][ni], ah, bl[ni]);
                mma_bf16(acc[mi][ni], al, bh[ni]);
            }
        }
    }

    float* eb = E + (size_t)nh * SSQ;
    const int tr = lane >> 2, tc = (lane & 3) * 2;
    #pragma unroll
    for (int mi = 0; mi < 4; mi++)
        #pragma unroll
        for (int ni = 0; ni < 4; ni++) {
            int rr = wm * 64 + mi * 16 + tr;
            int cc = wn * 32 + ni * 8 + tc;
            *(float2*)&eb[(size_t)rr * S + cc]     = make_float2(acc[mi][ni][0], acc[mi][ni][1]);
            *(float2*)&eb[(size_t)(rr+8) * S + cc] = make_float2(acc[mi][ni][2], acc[mi][ni][3]);
        }
}

// ---------------- fused BN + softmax + tensor-core AV -----------------------
// attn written to smem as split bf16 (hi/lo); v transposed to smem as split
// bf16; AV = 3-term split mma. Row stride 272 B (136 bf16) is conflict-free
// for ldmatrix phases (16 B offset per row within 128 B bank window).
#define AT_STR   136                       // bf16 elements per smem row
#define SAV_ATT  (128*AT_STR)              // attn tile elements
#define SAV_VT   (32*AT_STR)               // vT tile elements
#define SAV_SMEM ((2*SAV_ATT + 2*SAV_VT)*2) // 87040 bytes

__global__ void __launch_bounds__(256, 2)
softmax_av(const float* __restrict__ E,
           const float* __restrict__ scpe, const float* __restrict__ shpe,
           const float* __restrict__ V, float* __restrict__ O) {
    extern __shared__ __align__(16) char smc[];
    __nv_bfloat16* aH = (__nv_bfloat16*)smc;
    __nv_bfloat16* aL = aH + SAV_ATT;
    __nv_bfloat16* vH = aL + SAV_ATT;
    __nv_bfloat16* vL = vH + SAV_VT;
    const uint32_t aH32 = smem_u32(aH);
    const uint32_t aL32 = smem_u32(aL);
    const uint32_t vH32 = smem_u32(vH);
    const uint32_t vL32 = smem_u32(vL);

    const int nh = blockIdx.x;
    const int n = nh >> 3, h = nh & 7;
    const int t = threadIdx.x;
    const int lane = t & 31, warp = t >> 5;

    // load v [128 l x 32 d] fp32, split + transpose into vT[d][l]
    const float* vb = V + ((size_t)(n * S) * H + h) * D;
    #pragma unroll
    for (int i = 0; i < 16; i++) {
        int idx = t + i * 256;                 // 0..4095
        int l = idx >> 5, d = idx & 31;
        float val = vb[(size_t)l * (H * D) + d];
        __nv_bfloat16 hv = __float2bfloat16(val);
        vH[d * AT_STR + l] = hv;
        vL[d * AT_STR + l] = __float2bfloat16(val - __bfloat162float(hv));
    }

    // softmax: each warp 16 rows; write split-bf16 attn to smem
    const float* eb = E + (size_t)nh * SSQ;
    for (int rr = 0; rr < 16; rr++) {
        int row = warp * 16 + rr;
        const float* e = eb + (size_t)row * S;
        const float* sc = scpe + row * S;
        const float* sh = shpe + row * S;
        float v[4];
        float mx = -INFINITY;
        #pragma unroll
        for (int i = 0; i < 4; i++) {
            int ki = i * 32 + lane;
            v[i] = (e[ki] * sc[ki] + sh[ki]) * 0.0625f;
            mx = fmaxf(mx, v[i]);
        }
        #pragma unroll
        for (int off = 16; off > 0; off >>= 1)
            mx = fmaxf(mx, __shfl_xor_sync(0xffffffffu, mx, off));
        float sum = 0.f;
        #pragma unroll
        for (int i = 0; i < 4; i++) { v[i] = __expf(v[i] - mx); sum += v[i]; }
        #pragma unroll
        for (int off = 16; off > 0; off >>= 1)
            sum += __shfl_xor_sync(0xffffffffu, sum, off);
        float inv = 1.f / sum;
        #pragma unroll
        for (int i = 0; i < 4; i++) {
            float av = v[i] * inv;
            int ki = i * 32 + lane;
            __nv_bfloat16 hv = __float2bfloat16(av);
            aH[row * AT_STR + ki] = hv;
            aL[row * AT_STR + ki] = __float2bfloat16(av - __bfloat162float(hv));
        }
    }
    __syncthreads();

    // AV via mma: each warp owns 16 q-rows; N=32 (4 n8), K=128 (8 k16)
    float acc[4][4];
    #pragma unroll
    for (int ni = 0; ni < 4; ni++)
        #pragma unroll
        for (int x = 0; x < 4; x++) acc[ni][x] = 0.f;

    #pragma unroll
    for (int k = 0; k < 8; k++) {
        uint32_t ah[4], al[4];
        {
            int r = warp * 16 + (lane & 15);
            uint32_t cb = (uint32_t)(k * 32 + ((lane >> 4) << 4));
            ldm_x4(ah, aH32 + r * 272 + cb);
            ldm_x4(al, aL32 + r * 272 + cb);
        }
        uint32_t bh[4][2], bl[4][2];
        #pragma unroll
        for (int ni = 0; ni < 4; ni++) {
            int r = ni * 8 + (lane & 7);
            uint32_t cb = (uint32_t)(k * 32 + (((lane >> 3) & 1) << 4));
            ldm_x2(bh[ni], vH32 + r * 272 + cb);
            ldm_x2(bl[ni], vL32 + r * 272 + cb);
        }
        #pragma unroll
        for (int ni = 0; ni < 4; ni++) {
            mma_bf16(acc[ni], ah, bh[ni]);
            mma_bf16(acc[ni], ah, bl[ni]);
            mma_bf16(acc[ni], al, bh[ni]);
        }
    }

    // epilogue: o[q][d] fp32
    const int tr = lane >> 2, tc = (lane & 3) * 2;
    #pragma unroll
    for (int ni = 0; ni < 4; ni++) {
        int q0 = warp * 16 + tr;
        int cc = ni * 8 + tc;
        size_t b0 = ((size_t)(n * S + q0) * H + h) * D + cc;
        size_t b1 = ((size_t)(n * S + q0 + 8) * H + h) * D + cc;
        *(float2*)&O[b0] = make_float2(acc[ni][0], acc[ni][1]);
        *(float2*)&O[b1] = make_float2(acc[ni][2], acc[ni][3]);
    }
}

// ---------------------------------------------------------------------------
extern "C" void kernel_launch(void* const* d_in, const int* in_sizes, int n_in,
                              void* d_out, int out_size) {
    const float* x    = (const float*)d_in[0];
    const float* g_n  = (const float*)d_in[1];
    const float* b_n  = (const float*)d_in[2];
    const float* Wq   = (const float*)d_in[3];
    const float* Wk   = (const float*)d_in[4];
    const float* Wv   = (const float*)d_in[5];
    const float* Wo   = (const float*)d_in[6];
    const float* bo   = (const float*)d_in[7];
    const float* g_pe = (const float*)d_in[8];
    const float* b_pe = (const float*)d_in[9];
    const float* g0   = (const float*)d_in[10];
    const float* b0   = (const float*)d_in[11];
    const float* W0   = (const float*)d_in[12];
    const float* g1   = (const float*)d_in[13];
    const float* b1   = (const float*)d_in[14];
    const float* W1   = (const float*)d_in[15];
    float* out = (float*)d_out;

    float *v, *o, *e, *x1, *t2, *psum, *psq, *sc, *sh, *scpe, *shpe;
    __nv_bfloat16 *whi, *wlo, *qhi, *qlo, *khi, *klo;
    cudaGetSymbolAddress((void**)&v,    g_v);
    cudaGetSymbolAddress((void**)&o,    g_o);
    cudaGetSymbolAddress((void**)&e,    g_e);
    cudaGetSymbolAddress((void**)&x1,   g_x1);
    cudaGetSymbolAddress((void**)&t2,   g_t2);
    cudaGetSymbolAddress((void**)&psum, g_psum);
    cudaGetSymbolAddress((void**)&psq,  g_psq);
    cudaGetSymbolAddress((void**)&sc,   g_scale);
    cudaGetSymbolAddress((void**)&sh,   g_shift);
    cudaGetSymbolAddress((void**)&scpe, g_scale_pe);
    cudaGetSymbolAddress((void**)&shpe, g_shift_pe);
    cudaGetSymbolAddress((void**)&whi,  g_whi);
    cudaGetSymbolAddress((void**)&wlo,  g_wlo);
    cudaGetSymbolAddress((void**)&qhi,  g_qhi);
    cudaGetSymbolAddress((void**)&qlo,  g_qlo);
    cudaGetSymbolAddress((void**)&khi,  g_khi);
    cudaGetSymbolAddress((void**)&klo,  g_klo);

    cudaFuncSetAttribute(mma_gemm<2,true ,false,false,false,false>, cudaFuncAttributeMaxDynamicSharedMemorySize, MMA_SMEM);
    cudaFuncSetAttribute(mma_gemm<0,false,false,true ,true ,true >, cudaFuncAttributeMaxDynamicSharedMemorySize, MMA_SMEM);
    cudaFuncSetAttribute(mma_gemm<0,true ,true ,false,false,true >, cudaFuncAttributeMaxDynamicSharedMemorySize, MMA_SMEM);
    cudaFuncSetAttribute(mma_gemm<0,true ,true ,false,true ,false>, cudaFuncAttributeMaxDynamicSharedMemorySize, MMA_SMEM);
    cudaFuncSetAttribute(softmax_av, cudaFuncAttributeMaxDynamicSharedMemorySize, SAV_SMEM);

    // split all weights (one launch, no deps)
    splitW_all<<<512, 256>>>(Wq, Wk, Wv, Wo, W0, W1, whi, wlo);

    // BN over C on x
    bn_partial<<<dim3(1, 256), 256>>>(x, C, 128, psum, psq);
    bn_finalize_warp<<<C / 8, 256>>>(psum, psq, C, 256, 1.f / MROWS, g_n, b_n, sc, sh);

    // fused QKV GEMM (128-col tiles: tiles 0-1 -> q, 2-3 -> k, 4-5 -> v)
    dim3 gq(768 / 128, MROWS / 128);
    mma_gemm<2,true,false,false,false,false><<<gq, 256, MMA_SMEM>>>(x, sc, sh, whi, wlo,
        v, qhi, qlo, khi, klo, nullptr, nullptr, nullptr, nullptr, MROWS, 768, C);

    // energy (fp32 out)
    energy_mma<<<NHB, 256>>>(qhi, qlo, khi, klo, e);

    // BN over S*S on energy (16 partials)
    bn_partial<<<dim3(SSQ / 256, 16), 256>>>(e, SSQ, 128, psum, psq);
    bn_finalize<<<SSQ / 256, 256>>>(psum, psq, SSQ, 16, 1.f / NHB, g_pe, b_pe, scpe, shpe);

    // fused BN + softmax + tensor AV -> fp32 o
    softmax_av<<<NHB, 256, SAV_SMEM>>>(e, scpe, shpe, v, o);

    // x1 = o @ Wo^T + bo + x, with fused BN0 column partials
    dim3 go(C / 128, MROWS / 128);
    mma_gemm<0,false,false,true,true,true><<<go, 256, MMA_SMEM>>>(o, nullptr, nullptr,
        whi + WOFF_O, wlo + WOFF_O, x1, nullptr, nullptr, nullptr, nullptr, bo, x,
        psum, psq, MROWS, C, C);

    // BN0 finalize (partials already produced by Wo GEMM)
    bn_finalize_warp<<<C / 8, 256>>>(psum, psq, C, 256, 1.f / MROWS, g0, b0, sc, sh);

    // FFN0 GEMM (affine+relu fused on A), with fused BN1 column partials
    dim3 gf0(C2 / 128, MROWS / 128);
    mma_gemm<0,true,true,false,false,true><<<gf0, 256, MMA_SMEM>>>(x1, sc, sh,
        whi + WOFF_0, wlo + WOFF_0, t2, nullptr, nullptr, nullptr, nullptr, nullptr, nullptr,
        psum, psq, MROWS, C2, C);

    // BN1 finalize (partials already produced by FFN0 GEMM)
    bn_finalize_warp<<<C2 / 8, 256>>>(psum, psq, C2, 256, 1.f / MROWS, g1, b1, sc, sh);

    // FFN1 GEMM (affine+relu fused on A) + x1 residual -> out
    mma_gemm<0,true,true,false,true,false><<<go, 256, MMA_SMEM>>>(t2, sc, sh,
        whi + WOFF_1, wlo + WOFF_1, out, nullptr, nullptr, nullptr, nullptr, nullptr, x1,
        nullptr, nullptr, MROWS, C, C2);
}